// round 2
// baseline (speedup 1.0000x reference)
#include <cuda_runtime.h>
#include <cuda_bf16.h>
#include <math.h>

// ---------------------------------------------------------------------------
// Problem constants (fixed shapes for this problem instance)
// ---------------------------------------------------------------------------
#define NN     50000
#define DD     200
#define KK     3
#define R2D    474
#define EE     250000
#define BB     2048
#define HH     100
#define KD     (KK*DD)          // 600
#define NPAIR  3

// ---------------------------------------------------------------------------
// Scratch (static device globals -- no runtime allocation allowed)
// ---------------------------------------------------------------------------
__device__ float g_x[(size_t)NN * KD];        // x after PCA+tanh   (120 MB)
__device__ float g_agg[(size_t)NN * KD];      // attention aggregate (120 MB)
__device__ float g_edge_a[(size_t)EE * KK];   // exp(leaky(logit)) per edge,k
__device__ float g_denom[(size_t)NN * KK];    // per-(node,k) softmax denominator
__device__ float g_xi[(size_t)NPAIR * BB * DD];
__device__ float g_hmu[(size_t)NPAIR * BB * HH];
__device__ float g_hlv[(size_t)NPAIR * BB * HH];
__device__ float g_mu[(size_t)NPAIR * BB * DD];
__device__ float g_lv[(size_t)NPAIR * BB * DD];

// ---------------------------------------------------------------------------
// Zero scratch (agg + denom + loss slot)
// ---------------------------------------------------------------------------
__global__ void zero_scratch_kernel(float* __restrict__ loss_slot)
{
    size_t i = (size_t)blockIdx.x * blockDim.x + threadIdx.x;
    size_t stride = (size_t)gridDim.x * blockDim.x;
    float4* agg4 = reinterpret_cast<float4*>(g_agg);
    const size_t n4 = ((size_t)NN * KD) / 4;
    for (size_t j = i; j < n4; j += stride)
        agg4[j] = make_float4(0.f, 0.f, 0.f, 0.f);
    const size_t nden = (size_t)NN * KK;
    for (size_t j = i; j < nden; j += stride)
        g_denom[j] = 0.f;
    if (i == 0) *loss_slot = 0.f;
}

// ---------------------------------------------------------------------------
// Generic tiled fp32 GEMM with bias + activation.
// C[M,N] = act(A[M,Kd] @ B[Kd,N] (+ bias[N]))
// ACT: 0 = none, 1 = tanh, 2 = relu
// ---------------------------------------------------------------------------
#define GBM 64
#define GBN 64
#define GBK 16

template<int ACT, bool BIAS>
__global__ __launch_bounds__(256)
void gemm_act_kernel(const float* __restrict__ A, const float* __restrict__ B,
                     const float* __restrict__ bias, float* __restrict__ C,
                     int M, int N, int Kd)
{
    __shared__ float As[GBK][GBM];
    __shared__ float Bs[GBK][GBN];

    const int tid = threadIdx.x;
    const int tx = tid & 15;        // 0..15 -> N dir
    const int ty = tid >> 4;        // 0..15 -> M dir
    const int row0 = blockIdx.y * GBM;
    const int col0 = blockIdx.x * GBN;

    float acc[4][4];
#pragma unroll
    for (int i = 0; i < 4; i++)
#pragma unroll
        for (int j = 0; j < 4; j++) acc[i][j] = 0.f;

    for (int k0 = 0; k0 < Kd; k0 += GBK) {
        // load A tile (GBM x GBK), transposed into As[kk][m]
#pragma unroll
        for (int l = 0; l < 4; l++) {
            int linear = tid + l * 256;        // 0..1023
            int m  = linear >> 4;              // /16
            int kk = linear & 15;
            int gr = row0 + m, gk = k0 + kk;
            As[kk][m] = (gr < M && gk < Kd) ? A[(size_t)gr * Kd + gk] : 0.f;
        }
        // load B tile (GBK x GBN)
#pragma unroll
        for (int l = 0; l < 4; l++) {
            int linear = tid + l * 256;
            int n  = linear & 63;
            int kk = linear >> 6;
            int gk = k0 + kk, gc = col0 + n;
            Bs[kk][n] = (gk < Kd && gc < N) ? B[(size_t)gk * N + gc] : 0.f;
        }
        __syncthreads();

#pragma unroll
        for (int kk = 0; kk < GBK; kk++) {
            float a[4], b[4];
#pragma unroll
            for (int i = 0; i < 4; i++) a[i] = As[kk][ty * 4 + i];
#pragma unroll
            for (int j = 0; j < 4; j++) b[j] = Bs[kk][tx * 4 + j];
#pragma unroll
            for (int i = 0; i < 4; i++)
#pragma unroll
                for (int j = 0; j < 4; j++)
                    acc[i][j] += a[i] * b[j];
        }
        __syncthreads();
    }

#pragma unroll
    for (int i = 0; i < 4; i++) {
        int gr = row0 + ty * 4 + i;
        if (gr >= M) continue;
#pragma unroll
        for (int j = 0; j < 4; j++) {
            int gc = col0 + tx * 4 + j;
            if (gc >= N) continue;
            float v = acc[i][j];
            if (BIAS) v += bias[gc];
            if (ACT == 1) v = tanhf(v);
            else if (ACT == 2) v = fmaxf(v, 0.f);
            C[(size_t)gr * N + gc] = v;
        }
    }
}

// ---------------------------------------------------------------------------
// Edge pass A: per edge e, per k:
//   logit = leaky_relu( sum_d x[dst,k,d]*x[src,k,d]*r[et,d] * relw[et,k] )
//   a = exp(logit); edge_a[e,k] = a; denom[dst,k] += a   (atomic)
// (segment-max subtraction skipped: exactly cancels in alpha up to the 1e-10
//  eps scaled by e^M, |logit| <= ~1 so relative effect ~1e-10.)
// One warp per edge.
// ---------------------------------------------------------------------------
__global__ __launch_bounds__(256)
void edge_logits_kernel(const int* __restrict__ ei, const int* __restrict__ etype,
                        const float* __restrict__ r, const float* __restrict__ relw)
{
    int w    = (blockIdx.x * blockDim.x + threadIdx.x) >> 5;
    int lane = threadIdx.x & 31;
    if (w >= EE) return;

    int dst = ei[w];
    int src = ei[EE + w];
    int t   = etype[w];

    const float* xd = g_x + (size_t)dst * KD;
    const float* xs = g_x + (size_t)src * KD;
    const float* rr = r   + (size_t)t * DD;

    float rv[7];
#pragma unroll
    for (int i = 0; i < 7; i++) {
        int d = lane + 32 * i;
        rv[i] = (d < DD) ? rr[d] : 0.f;
    }

#pragma unroll
    for (int k = 0; k < KK; k++) {
        float s = 0.f;
#pragma unroll
        for (int i = 0; i < 7; i++) {
            int d = lane + 32 * i;
            if (d < DD) s += xd[k * DD + d] * xs[k * DD + d] * rv[i];
        }
#pragma unroll
        for (int o = 16; o > 0; o >>= 1)
            s += __shfl_xor_sync(0xffffffffu, s, o);
        if (lane == 0) {
            float l = s * relw[t * KK + k];
            l = (l > 0.f) ? l : 0.2f * l;
            float a = expf(l);
            g_edge_a[(size_t)w * KK + k] = a;
            atomicAdd(&g_denom[(size_t)dst * KK + k], a);
        }
    }
}

// ---------------------------------------------------------------------------
// Edge pass C: agg[dst,k,d] += alpha * x[src,k,d]*r[et,d]
// alpha = edge_a / (denom + 1e-10). One warp per edge, float4 inner reads,
// scalar atomic adds (RED.E.ADD.F32) into g_agg.
// ---------------------------------------------------------------------------
__global__ __launch_bounds__(256)
void edge_agg_kernel(const int* __restrict__ ei, const int* __restrict__ etype,
                     const float* __restrict__ r)
{
    int w    = (blockIdx.x * blockDim.x + threadIdx.x) >> 5;
    int lane = threadIdx.x & 31;
    if (w >= EE) return;

    int dst = ei[w];
    int src = ei[EE + w];
    int t   = etype[w];

    const float*  xs  = g_x + (size_t)src * KD;
    const float4* rr4 = reinterpret_cast<const float4*>(r + (size_t)t * DD);
    float*        ag  = g_agg + (size_t)dst * KD;

#pragma unroll
    for (int k = 0; k < KK; k++) {
        float alpha = g_edge_a[(size_t)w * KK + k] /
                      (g_denom[(size_t)dst * KK + k] + 1e-10f);
        const float4* xs4 = reinterpret_cast<const float4*>(xs + k * DD);
        // 50 float4 per k; lanes handle j = lane and j = lane+32 (lanes < 18)
#pragma unroll
        for (int rep = 0; rep < 2; rep++) {
            int j = lane + rep * 32;
            if (j < DD / 4) {
                float4 v = xs4[j];
                float4 rv = rr4[j];
                int base = k * DD + 4 * j;
                atomicAdd(&ag[base + 0], alpha * v.x * rv.x);
                atomicAdd(&ag[base + 1], alpha * v.y * rv.y);
                atomicAdd(&ag[base + 2], alpha * v.z * rv.z);
                atomicAdd(&ag[base + 3], alpha * v.w * rv.w);
            }
        }
    }
}

// ---------------------------------------------------------------------------
// Gather outputs: sub_emb, rel_emb_single, and xi (MI input) from x_new.
// One block per batch element.
// ---------------------------------------------------------------------------
__global__ __launch_bounds__(256)
void gather_kernel(const float* __restrict__ xnew, const float* __restrict__ init_rel,
                   const int* __restrict__ sub, const int* __restrict__ rel,
                   float* __restrict__ sub_emb, float* __restrict__ rel_emb)
{
    int b = blockIdx.x;
    int t = threadIdx.x;
    int sb = sub[b];
    const float* srcx = xnew + (size_t)sb * KD;
    float* se = sub_emb + (size_t)b * KD;
    for (int j = t; j < KD; j += 256) se[j] = srcx[j];

    int rb = rel[b];
    const float* srcr = init_rel + (size_t)rb * DD;
    float* re = rel_emb + (size_t)b * DD;
    for (int j = t; j < DD; j += 256) re[j] = srcr[j];

    // xi slices: pi = {0,0,1} -> k index of source slice
    for (int j = t; j < DD; j += 256) {
        float v0 = srcx[j];           // k = 0
        float v1 = srcx[DD + j];      // k = 1
        g_xi[((size_t)0 * BB + b) * DD + j] = v0;
        g_xi[((size_t)1 * BB + b) * DD + j] = v0;
        g_xi[((size_t)2 * BB + b) * DD + j] = v1;
    }
}

// ---------------------------------------------------------------------------
// MI loss reduction. One warp per (pair, batch element).
// loss += sum_d ((mu - yj_neg)^2 - (mu - yj)^2) * exp(-logvar) / (2*B)
// pj = {1,2,2}
// ---------------------------------------------------------------------------
__global__ __launch_bounds__(256)
void mi_loss_kernel(const float* __restrict__ xnew,
                    const int* __restrict__ sub, const int* __restrict__ perm,
                    float* __restrict__ loss_out)
{
    int w    = (blockIdx.x * blockDim.x + threadIdx.x) >> 5;
    int lane = threadIdx.x & 31;
    if (w >= NPAIR * BB) return;
    int p = w / BB;
    int b = w % BB;
    int pj = (p == 0) ? 1 : 2;

    const float* mup = g_mu + ((size_t)p * BB + b) * DD;
    const float* lvp = g_lv + ((size_t)p * BB + b) * DD;
    int sb  = sub[b];
    int sbn = sub[perm[b]];
    const float* yj  = xnew + (size_t)sb  * KD + pj * DD;
    const float* yjn = xnew + (size_t)sbn * KD + pj * DD;

    float s = 0.f;
    for (int d = lane; d < DD; d += 32) {
        float m  = mup[d];
        float iv = expf(-lvp[d]);
        float dp = m - yj[d];
        float dn = m - yjn[d];
        s += (dn * dn - dp * dp) * iv;
    }
#pragma unroll
    for (int o = 16; o > 0; o >>= 1)
        s += __shfl_xor_sync(0xffffffffu, s, o);
    if (lane == 0)
        atomicAdd(loss_out, s / (2.0f * BB));
}

// ---------------------------------------------------------------------------
// Launch
// ---------------------------------------------------------------------------
extern "C" void kernel_launch(void* const* d_in, const int* in_sizes, int n_in,
                              void* d_out, int out_size)
{
    // ---- input binding: detect ordering from in_sizes -------------------
    // setup_inputs() dict order starts with edge_index (2*E = 500000 ints);
    // reference() signature order starts with init_embed (N*D = 10M floats).
    const float *init_embed, *init_rel, *pca_W, *pca_b, *rel_weight, *W_ent;
    const float *mu_w1, *mu_b1, *mu_w2, *mu_b2, *lv_w1, *lv_b1, *lv_w2, *lv_b2;
    const int *edge_index, *edge_type, *sub, *rel, *perm;

    if (in_sizes[0] == 2 * EE) {
        // dict order: edge_index, edge_type, sub, rel, perm, init_embed,
        // init_rel, pca_W, pca_b, rel_weight, W_ent, W_rel, mu_w1, mu_b1,
        // mu_w2, mu_b2, lv_w1, lv_b1, lv_w2, lv_b2
        edge_index = (const int*)d_in[0];
        edge_type  = (const int*)d_in[1];
        sub        = (const int*)d_in[2];
        rel        = (const int*)d_in[3];
        perm       = (const int*)d_in[4];
        init_embed = (const float*)d_in[5];
        init_rel   = (const float*)d_in[6];
        pca_W      = (const float*)d_in[7];
        pca_b      = (const float*)d_in[8];
        rel_weight = (const float*)d_in[9];
        W_ent      = (const float*)d_in[10];
        /* d_in[11] = W_rel (dead) */
        mu_w1 = (const float*)d_in[12];
        mu_b1 = (const float*)d_in[13];
        mu_w2 = (const float*)d_in[14];
        mu_b2 = (const float*)d_in[15];
        lv_w1 = (const float*)d_in[16];
        lv_b1 = (const float*)d_in[17];
        lv_w2 = (const float*)d_in[18];
        lv_b2 = (const float*)d_in[19];
    } else {
        // signature order
        init_embed = (const float*)d_in[0];
        init_rel   = (const float*)d_in[1];
        pca_W      = (const float*)d_in[2];
        pca_b      = (const float*)d_in[3];
        rel_weight = (const float*)d_in[4];
        W_ent      = (const float*)d_in[5];
        /* d_in[6] = W_rel (dead) */
        mu_w1 = (const float*)d_in[7];
        mu_b1 = (const float*)d_in[8];
        mu_w2 = (const float*)d_in[9];
        mu_b2 = (const float*)d_in[10];
        lv_w1 = (const float*)d_in[11];
        lv_b1 = (const float*)d_in[12];
        lv_w2 = (const float*)d_in[13];
        lv_b2 = (const float*)d_in[14];
        edge_index = (const int*)d_in[15];
        edge_type  = (const int*)d_in[16];
        sub        = (const int*)d_in[17];
        rel        = (const int*)d_in[18];
        perm       = (const int*)d_in[19];
    }

    float* out = (float*)d_out;
    const size_t SUB_OFF  = 0;
    const size_t REL_OFF  = (size_t)BB * KD;                 // 1,228,800
    const size_t X_OFF    = REL_OFF + (size_t)BB * DD;       // 1,638,400
    const size_t LOSS_OFF = X_OFF + (size_t)NN * KD;         // 31,638,400

    float* sub_emb = out + SUB_OFF;
    float* rel_emb = out + REL_OFF;
    float* xnew    = out + X_OFF;
    float* loss    = out + LOSS_OFF;

    // resolve device symbol addresses (pure address queries, no allocation)
    float *p_x, *p_agg, *p_xi, *p_hmu, *p_hlv, *p_mu, *p_lv;
    cudaGetSymbolAddress((void**)&p_x,   g_x);
    cudaGetSymbolAddress((void**)&p_agg, g_agg);
    cudaGetSymbolAddress((void**)&p_xi,  g_xi);
    cudaGetSymbolAddress((void**)&p_hmu, g_hmu);
    cudaGetSymbolAddress((void**)&p_hlv, g_hlv);
    cudaGetSymbolAddress((void**)&p_mu,  g_mu);
    cudaGetSymbolAddress((void**)&p_lv,  g_lv);

    // 1. zero agg / denom / loss
    zero_scratch_kernel<<<4096, 256>>>(loss);

    // 2. x = tanh(init_embed @ pca_W + pca_b)   (50000 x 600)
    {
        dim3 g((KD + GBN - 1) / GBN, (NN + GBM - 1) / GBM);
        gemm_act_kernel<1, true><<<g, 256>>>(init_embed, pca_W, pca_b, p_x,
                                             NN, KD, DD);
    }

    // 3. edge logits -> edge_a + denom
    {
        int warps = EE;
        int blocks = (warps * 32 + 255) / 256;
        edge_logits_kernel<<<blocks, 256>>>(edge_index, edge_type,
                                            init_rel, rel_weight);
    }

    // 4. edge aggregation -> g_agg
    {
        int warps = EE;
        int blocks = (warps * 32 + 255) / 256;
        edge_agg_kernel<<<blocks, 256>>>(edge_index, edge_type, init_rel);
    }

    // 5. x_new = tanh(agg @ W_ent)  ((N*K) x 200) -> d_out X region
    {
        dim3 g((DD + GBN - 1) / GBN, (NN * KK + GBM - 1) / GBM);
        gemm_act_kernel<1, false><<<g, 256>>>(p_agg, W_ent, nullptr, xnew,
                                              NN * KK, DD, DD);
    }

    // 6. gathers: sub_emb, rel_emb, xi
    gather_kernel<<<BB, 256>>>(xnew, init_rel, sub, rel, sub_emb, rel_emb);

    // 7. MI head per pair: two 2-layer MLPs
    for (int p = 0; p < NPAIR; p++) {
        const float* xi_p = p_xi + (size_t)p * BB * DD;
        {   // hid_mu = relu(xi @ mu_w1[p] + mu_b1[p])   (B x H)
            dim3 g((HH + GBN - 1) / GBN, (BB + GBM - 1) / GBM);
            gemm_act_kernel<2, true><<<g, 256>>>(xi_p,
                mu_w1 + (size_t)p * DD * HH, mu_b1 + (size_t)p * HH,
                p_hmu + (size_t)p * BB * HH, BB, HH, DD);
        }
        {   // mu = hid_mu @ mu_w2[p] + mu_b2[p]         (B x D)
            dim3 g((DD + GBN - 1) / GBN, (BB + GBM - 1) / GBM);
            gemm_act_kernel<0, true><<<g, 256>>>(p_hmu + (size_t)p * BB * HH,
                mu_w2 + (size_t)p * HH * DD, mu_b2 + (size_t)p * DD,
                p_mu + (size_t)p * BB * DD, BB, DD, HH);
        }
        {   // hid_lv = relu(xi @ lv_w1[p] + lv_b1[p])
            dim3 g((HH + GBN - 1) / GBN, (BB + GBM - 1) / GBM);
            gemm_act_kernel<2, true><<<g, 256>>>(xi_p,
                lv_w1 + (size_t)p * DD * HH, lv_b1 + (size_t)p * HH,
                p_hlv + (size_t)p * BB * HH, BB, HH, DD);
        }
        {   // logvar = tanh(hid_lv @ lv_w2[p] + lv_b2[p])
            gemm_act_kernel<1, true><<<dim3((DD + GBN - 1) / GBN,
                                            (BB + GBM - 1) / GBM), 256>>>(
                p_hlv + (size_t)p * BB * HH,
                lv_w2 + (size_t)p * HH * DD, lv_b2 + (size_t)p * DD,
                p_lv + (size_t)p * BB * DD, BB, DD, HH);
        }
    }

    // 8. MI loss reduction
    {
        int warps = NPAIR * BB;
        int blocks = (warps * 32 + 255) / 256;
        mi_loss_kernel<<<blocks, 256>>>(xnew, sub, perm, loss);
    }

    (void)n_in; (void)out_size;
}

// round 3
// speedup vs baseline: 1.3523x; 1.3523x over previous
#include <cuda_runtime.h>
#include <cuda_bf16.h>
#include <math.h>
#include <mma.h>

using namespace nvcuda;

// ---------------------------------------------------------------------------
// Problem constants (fixed shapes for this problem instance)
// ---------------------------------------------------------------------------
#define NN     50000
#define DD     200
#define KK     3
#define R2D    474
#define EE     250000
#define BB     2048
#define HH     100
#define KD     (KK*DD)          // 600
#define NPAIR  3

// ---------------------------------------------------------------------------
// Scratch (static device globals -- no runtime allocation allowed)
// ---------------------------------------------------------------------------
__device__ float g_x[(size_t)NN * KD];        // x after PCA+tanh   (120 MB)
__device__ float g_agg[(size_t)NN * KD];      // attention aggregate (120 MB)
__device__ float g_edge_a[(size_t)EE * KK];   // exp(leaky(logit)) per edge,k
__device__ float g_denom[(size_t)NN * KK];    // per-(node,k) softmax denominator
__device__ float g_xi[(size_t)NPAIR * BB * DD];
__device__ float g_hmu[(size_t)NPAIR * BB * HH];
__device__ float g_hlv[(size_t)NPAIR * BB * HH];
__device__ float g_mu[(size_t)NPAIR * BB * DD];
__device__ float g_lv[(size_t)NPAIR * BB * DD];

// ---------------------------------------------------------------------------
// Zero scratch (agg + denom + loss slot)
// ---------------------------------------------------------------------------
__global__ void zero_scratch_kernel(float* __restrict__ loss_slot)
{
    size_t i = (size_t)blockIdx.x * blockDim.x + threadIdx.x;
    size_t stride = (size_t)gridDim.x * blockDim.x;
    float4* agg4 = reinterpret_cast<float4*>(g_agg);
    const size_t n4 = ((size_t)NN * KD) / 4;
    for (size_t j = i; j < n4; j += stride)
        agg4[j] = make_float4(0.f, 0.f, 0.f, 0.f);
    const size_t nden = (size_t)NN * KK;
    for (size_t j = i; j < nden; j += stride)
        g_denom[j] = 0.f;
    if (i == 0) *loss_slot = 0.f;
}

// ---------------------------------------------------------------------------
// tf32 tensor-core GEMM with bias + activation.
// C[M,N] = act(A[M,Kd] @ B[Kd,N] (+ bias[N]))
// ACT: 0 = none, 1 = tanh, 2 = relu
// Block tile 128x64, 8 warps, each warp 32x32 (2x2 m16n16k8 tf32 fragments).
// K staged 16 wide in SMEM with zero padding (handles all tails).
// ---------------------------------------------------------------------------
#define TM 128
#define TN 64
#define TKC 16

template<int ACT, bool BIAS>
__global__ __launch_bounds__(256)
void gemm_tf32_kernel(const float* __restrict__ A, const float* __restrict__ B,
                      const float* __restrict__ bias, float* __restrict__ C,
                      int M, int N, int Kd)
{
    __shared__ float As[TM][TKC + 4];   // 128 x 20 floats = 10240 B
    __shared__ float Bs[TKC][TN + 4];   // 16 x 68 floats  = 4352 B
    __shared__ float Cs[TM][TN];        // 32768 B   (total 47360 B < 48K)

    const int tid  = threadIdx.x;
    const int warp = tid >> 5;
    const int wm   = warp >> 1;   // 0..3  (M dir, 32 rows each)
    const int wn   = warp & 1;    // 0..1  (N dir, 32 cols each)
    const int row0 = blockIdx.y * TM;
    const int col0 = blockIdx.x * TN;

    wmma::fragment<wmma::accumulator, 16, 16, 8, float> acc[2][2];
#pragma unroll
    for (int i = 0; i < 2; i++)
#pragma unroll
        for (int j = 0; j < 2; j++)
            wmma::fill_fragment(acc[i][j], 0.0f);

    for (int k0 = 0; k0 < Kd; k0 += TKC) {
        // load A tile: 128x16 = 2048 elements, 8 per thread
#pragma unroll
        for (int l = 0; l < 8; l++) {
            int idx = tid + l * 256;
            int m  = idx >> 4;
            int kk = idx & 15;
            int gr = row0 + m, gk = k0 + kk;
            As[m][kk] = (gr < M && gk < Kd) ? A[(size_t)gr * Kd + gk] : 0.f;
        }
        // load B tile: 16x64 = 1024 elements, 4 per thread
#pragma unroll
        for (int l = 0; l < 4; l++) {
            int idx = tid + l * 256;
            int n  = idx & 63;
            int kk = idx >> 6;
            int gk = k0 + kk, gc = col0 + n;
            Bs[kk][n] = (gk < Kd && gc < N) ? B[(size_t)gk * N + gc] : 0.f;
        }
        __syncthreads();

#pragma unroll
        for (int ks = 0; ks < TKC; ks += 8) {
            wmma::fragment<wmma::matrix_a, 16, 16, 8,
                           wmma::precision::tf32, wmma::row_major> fa[2];
            wmma::fragment<wmma::matrix_b, 16, 16, 8,
                           wmma::precision::tf32, wmma::row_major> fb[2];
#pragma unroll
            for (int i = 0; i < 2; i++) {
                wmma::load_matrix_sync(fa[i], &As[wm * 32 + i * 16][ks], TKC + 4);
#pragma unroll
                for (int t = 0; t < fa[i].num_elements; t++)
                    fa[i].x[t] = wmma::__float_to_tf32(fa[i].x[t]);
            }
#pragma unroll
            for (int j = 0; j < 2; j++) {
                wmma::load_matrix_sync(fb[j], &Bs[ks][wn * 32 + j * 16], TN + 4);
#pragma unroll
                for (int t = 0; t < fb[j].num_elements; t++)
                    fb[j].x[t] = wmma::__float_to_tf32(fb[j].x[t]);
            }
#pragma unroll
            for (int i = 0; i < 2; i++)
#pragma unroll
                for (int j = 0; j < 2; j++)
                    wmma::mma_sync(acc[i][j], fa[i], fb[j], acc[i][j]);
        }
        __syncthreads();
    }

    // epilogue: stage C tile in SMEM, then bias/activation + bounded store
#pragma unroll
    for (int i = 0; i < 2; i++)
#pragma unroll
        for (int j = 0; j < 2; j++)
            wmma::store_matrix_sync(&Cs[wm * 32 + i * 16][wn * 32 + j * 16],
                                    acc[i][j], TN, wmma::mem_row_major);
    __syncthreads();

#pragma unroll
    for (int l = 0; l < (TM * TN) / 256; l++) {
        int idx = tid + l * 256;
        int m = idx / TN;
        int n = idx % TN;
        int gr = row0 + m, gc = col0 + n;
        if (gr < M && gc < N) {
            float v = Cs[m][n];
            if (BIAS) v += bias[gc];
            if (ACT == 1) v = tanhf(v);
            else if (ACT == 2) v = fmaxf(v, 0.f);
            C[(size_t)gr * N + gc] = v;
        }
    }
}

// ---------------------------------------------------------------------------
// Edge pass A: per edge e, per k:
//   logit = leaky_relu( sum_d x[dst,k,d]*x[src,k,d]*r[et,d] * relw[et,k] )
//   a = exp(logit); edge_a[e,k] = a; denom[dst,k] += a   (atomic)
// (segment-max subtraction skipped: exactly cancels in alpha up to the 1e-10
//  eps scaled by e^M, |logit| <= ~1 so relative effect ~1e-10.)
// One warp per edge.
// ---------------------------------------------------------------------------
__global__ __launch_bounds__(256)
void edge_logits_kernel(const int* __restrict__ ei, const int* __restrict__ etype,
                        const float* __restrict__ r, const float* __restrict__ relw)
{
    int w    = (blockIdx.x * blockDim.x + threadIdx.x) >> 5;
    int lane = threadIdx.x & 31;
    if (w >= EE) return;

    int dst = ei[w];
    int src = ei[EE + w];
    int t   = etype[w];

    const float* xd = g_x + (size_t)dst * KD;
    const float* xs = g_x + (size_t)src * KD;
    const float* rr = r   + (size_t)t * DD;

    float rv[7];
#pragma unroll
    for (int i = 0; i < 7; i++) {
        int d = lane + 32 * i;
        rv[i] = (d < DD) ? rr[d] : 0.f;
    }

#pragma unroll
    for (int k = 0; k < KK; k++) {
        float s = 0.f;
#pragma unroll
        for (int i = 0; i < 7; i++) {
            int d = lane + 32 * i;
            if (d < DD) s += xd[k * DD + d] * xs[k * DD + d] * rv[i];
        }
#pragma unroll
        for (int o = 16; o > 0; o >>= 1)
            s += __shfl_xor_sync(0xffffffffu, s, o);
        if (lane == 0) {
            float l = s * relw[t * KK + k];
            l = (l > 0.f) ? l : 0.2f * l;
            float a = expf(l);
            g_edge_a[(size_t)w * KK + k] = a;
            atomicAdd(&g_denom[(size_t)dst * KK + k], a);
        }
    }
}

// ---------------------------------------------------------------------------
// Edge pass C: agg[dst,k,d] += alpha * x[src,k,d]*r[et,d]
// ---------------------------------------------------------------------------
__global__ __launch_bounds__(256)
void edge_agg_kernel(const int* __restrict__ ei, const int* __restrict__ etype,
                     const float* __restrict__ r)
{
    int w    = (blockIdx.x * blockDim.x + threadIdx.x) >> 5;
    int lane = threadIdx.x & 31;
    if (w >= EE) return;

    int dst = ei[w];
    int src = ei[EE + w];
    int t   = etype[w];

    const float*  xs  = g_x + (size_t)src * KD;
    const float4* rr4 = reinterpret_cast<const float4*>(r + (size_t)t * DD);
    float*        ag  = g_agg + (size_t)dst * KD;

#pragma unroll
    for (int k = 0; k < KK; k++) {
        float alpha = g_edge_a[(size_t)w * KK + k] /
                      (g_denom[(size_t)dst * KK + k] + 1e-10f);
        const float4* xs4 = reinterpret_cast<const float4*>(xs + k * DD);
#pragma unroll
        for (int rep = 0; rep < 2; rep++) {
            int j = lane + rep * 32;
            if (j < DD / 4) {
                float4 v = xs4[j];
                float4 rv = rr4[j];
                int base = k * DD + 4 * j;
                atomicAdd(&ag[base + 0], alpha * v.x * rv.x);
                atomicAdd(&ag[base + 1], alpha * v.y * rv.y);
                atomicAdd(&ag[base + 2], alpha * v.z * rv.z);
                atomicAdd(&ag[base + 3], alpha * v.w * rv.w);
            }
        }
    }
}

// ---------------------------------------------------------------------------
// Gather outputs: sub_emb, rel_emb_single, and xi (MI input) from x_new.
// ---------------------------------------------------------------------------
__global__ __launch_bounds__(256)
void gather_kernel(const float* __restrict__ xnew, const float* __restrict__ init_rel,
                   const int* __restrict__ sub, const int* __restrict__ rel,
                   float* __restrict__ sub_emb, float* __restrict__ rel_emb)
{
    int b = blockIdx.x;
    int t = threadIdx.x;
    int sb = sub[b];
    const float* srcx = xnew + (size_t)sb * KD;
    float* se = sub_emb + (size_t)b * KD;
    for (int j = t; j < KD; j += 256) se[j] = srcx[j];

    int rb = rel[b];
    const float* srcr = init_rel + (size_t)rb * DD;
    float* re = rel_emb + (size_t)b * DD;
    for (int j = t; j < DD; j += 256) re[j] = srcr[j];

    for (int j = t; j < DD; j += 256) {
        float v0 = srcx[j];           // k = 0
        float v1 = srcx[DD + j];      // k = 1
        g_xi[((size_t)0 * BB + b) * DD + j] = v0;
        g_xi[((size_t)1 * BB + b) * DD + j] = v0;
        g_xi[((size_t)2 * BB + b) * DD + j] = v1;
    }
}

// ---------------------------------------------------------------------------
// MI loss reduction. One warp per (pair, batch element).
// ---------------------------------------------------------------------------
__global__ __launch_bounds__(256)
void mi_loss_kernel(const float* __restrict__ xnew,
                    const int* __restrict__ sub, const int* __restrict__ perm,
                    float* __restrict__ loss_out)
{
    int w    = (blockIdx.x * blockDim.x + threadIdx.x) >> 5;
    int lane = threadIdx.x & 31;
    if (w >= NPAIR * BB) return;
    int p = w / BB;
    int b = w % BB;
    int pj = (p == 0) ? 1 : 2;

    const float* mup = g_mu + ((size_t)p * BB + b) * DD;
    const float* lvp = g_lv + ((size_t)p * BB + b) * DD;
    int sb  = sub[b];
    int sbn = sub[perm[b]];
    const float* yj  = xnew + (size_t)sb  * KD + pj * DD;
    const float* yjn = xnew + (size_t)sbn * KD + pj * DD;

    float s = 0.f;
    for (int d = lane; d < DD; d += 32) {
        float m  = mup[d];
        float iv = expf(-lvp[d]);
        float dp = m - yj[d];
        float dn = m - yjn[d];
        s += (dn * dn - dp * dp) * iv;
    }
#pragma unroll
    for (int o = 16; o > 0; o >>= 1)
        s += __shfl_xor_sync(0xffffffffu, s, o);
    if (lane == 0)
        atomicAdd(loss_out, s / (2.0f * BB));
}

// ---------------------------------------------------------------------------
// Launch
// ---------------------------------------------------------------------------
extern "C" void kernel_launch(void* const* d_in, const int* in_sizes, int n_in,
                              void* d_out, int out_size)
{
    // ---- input binding: detect ordering from in_sizes -------------------
    const float *init_embed, *init_rel, *pca_W, *pca_b, *rel_weight, *W_ent;
    const float *mu_w1, *mu_b1, *mu_w2, *mu_b2, *lv_w1, *lv_b1, *lv_w2, *lv_b2;
    const int *edge_index, *edge_type, *sub, *rel, *perm;

    if (in_sizes[0] == 2 * EE) {
        // dict order
        edge_index = (const int*)d_in[0];
        edge_type  = (const int*)d_in[1];
        sub        = (const int*)d_in[2];
        rel        = (const int*)d_in[3];
        perm       = (const int*)d_in[4];
        init_embed = (const float*)d_in[5];
        init_rel   = (const float*)d_in[6];
        pca_W      = (const float*)d_in[7];
        pca_b      = (const float*)d_in[8];
        rel_weight = (const float*)d_in[9];
        W_ent      = (const float*)d_in[10];
        /* d_in[11] = W_rel (dead) */
        mu_w1 = (const float*)d_in[12];
        mu_b1 = (const float*)d_in[13];
        mu_w2 = (const float*)d_in[14];
        mu_b2 = (const float*)d_in[15];
        lv_w1 = (const float*)d_in[16];
        lv_b1 = (const float*)d_in[17];
        lv_w2 = (const float*)d_in[18];
        lv_b2 = (const float*)d_in[19];
    } else {
        // signature order
        init_embed = (const float*)d_in[0];
        init_rel   = (const float*)d_in[1];
        pca_W      = (const float*)d_in[2];
        pca_b      = (const float*)d_in[3];
        rel_weight = (const float*)d_in[4];
        W_ent      = (const float*)d_in[5];
        mu_w1 = (const float*)d_in[7];
        mu_b1 = (const float*)d_in[8];
        mu_w2 = (const float*)d_in[9];
        mu_b2 = (const float*)d_in[10];
        lv_w1 = (const float*)d_in[11];
        lv_b1 = (const float*)d_in[12];
        lv_w2 = (const float*)d_in[13];
        lv_b2 = (const float*)d_in[14];
        edge_index = (const int*)d_in[15];
        edge_type  = (const int*)d_in[16];
        sub        = (const int*)d_in[17];
        rel        = (const int*)d_in[18];
        perm       = (const int*)d_in[19];
    }

    float* out = (float*)d_out;
    const size_t SUB_OFF  = 0;
    const size_t REL_OFF  = (size_t)BB * KD;                 // 1,228,800
    const size_t X_OFF    = REL_OFF + (size_t)BB * DD;       // 1,638,400
    const size_t LOSS_OFF = X_OFF + (size_t)NN * KD;         // 31,638,400

    float* sub_emb = out + SUB_OFF;
    float* rel_emb = out + REL_OFF;
    float* xnew    = out + X_OFF;
    float* loss    = out + LOSS_OFF;

    float *p_x, *p_agg, *p_xi, *p_hmu, *p_hlv, *p_mu, *p_lv;
    cudaGetSymbolAddress((void**)&p_x,   g_x);
    cudaGetSymbolAddress((void**)&p_agg, g_agg);
    cudaGetSymbolAddress((void**)&p_xi,  g_xi);
    cudaGetSymbolAddress((void**)&p_hmu, g_hmu);
    cudaGetSymbolAddress((void**)&p_hlv, g_hlv);
    cudaGetSymbolAddress((void**)&p_mu,  g_mu);
    cudaGetSymbolAddress((void**)&p_lv,  g_lv);

    // 1. zero agg / denom / loss
    zero_scratch_kernel<<<4096, 256>>>(loss);

    // 2. x = tanh(init_embed @ pca_W + pca_b)   (50000 x 600)
    {
        dim3 g((KD + TN - 1) / TN, (NN + TM - 1) / TM);
        gemm_tf32_kernel<1, true><<<g, 256>>>(init_embed, pca_W, pca_b, p_x,
                                              NN, KD, DD);
    }

    // 3. edge logits -> edge_a + denom
    {
        int blocks = (EE * 32 + 255) / 256;
        edge_logits_kernel<<<blocks, 256>>>(edge_index, edge_type,
                                            init_rel, rel_weight);
    }

    // 4. edge aggregation -> g_agg
    {
        int blocks = (EE * 32 + 255) / 256;
        edge_agg_kernel<<<blocks, 256>>>(edge_index, edge_type, init_rel);
    }

    // 5. x_new = tanh(agg @ W_ent)  ((N*K) x 200) -> d_out X region
    {
        dim3 g((DD + TN - 1) / TN, (NN * KK + TM - 1) / TM);
        gemm_tf32_kernel<1, false><<<g, 256>>>(p_agg, W_ent, nullptr, xnew,
                                               NN * KK, DD, DD);
    }

    // 6. gathers: sub_emb, rel_emb, xi
    gather_kernel<<<BB, 256>>>(xnew, init_rel, sub, rel, sub_emb, rel_emb);

    // 7. MI head per pair: two 2-layer MLPs
    for (int p = 0; p < NPAIR; p++) {
        const float* xi_p = p_xi + (size_t)p * BB * DD;
        {   // hid_mu = relu(xi @ mu_w1[p] + mu_b1[p])   (B x H)
            dim3 g((HH + TN - 1) / TN, (BB + TM - 1) / TM);
            gemm_tf32_kernel<2, true><<<g, 256>>>(xi_p,
                mu_w1 + (size_t)p * DD * HH, mu_b1 + (size_t)p * HH,
                p_hmu + (size_t)p * BB * HH, BB, HH, DD);
        }
        {   // mu = hid_mu @ mu_w2[p] + mu_b2[p]         (B x D)
            dim3 g((DD + TN - 1) / TN, (BB + TM - 1) / TM);
            gemm_tf32_kernel<0, true><<<g, 256>>>(p_hmu + (size_t)p * BB * HH,
                mu_w2 + (size_t)p * HH * DD, mu_b2 + (size_t)p * DD,
                p_mu + (size_t)p * BB * DD, BB, DD, HH);
        }
        {   // hid_lv = relu(xi @ lv_w1[p] + lv_b1[p])
            dim3 g((HH + TN - 1) / TN, (BB + TM - 1) / TM);
            gemm_tf32_kernel<2, true><<<g, 256>>>(xi_p,
                lv_w1 + (size_t)p * DD * HH, lv_b1 + (size_t)p * HH,
                p_hlv + (size_t)p * BB * HH, BB, HH, DD);
        }
        {   // logvar = tanh(hid_lv @ lv_w2[p] + lv_b2[p])
            dim3 g((DD + TN - 1) / TN, (BB + TM - 1) / TM);
            gemm_tf32_kernel<1, true><<<g, 256>>>(p_hlv + (size_t)p * BB * HH,
                lv_w2 + (size_t)p * HH * DD, lv_b2 + (size_t)p * DD,
                p_lv + (size_t)p * BB * DD, BB, DD, HH);
        }
    }

    // 8. MI loss reduction
    {
        int blocks = (NPAIR * BB * 32 + 255) / 256;
        mi_loss_kernel<<<blocks, 256>>>(xnew, sub, perm, loss);
    }

    (void)n_in; (void)out_size;
}

// round 4
// speedup vs baseline: 1.6319x; 1.2068x over previous
#include <cuda_runtime.h>
#include <cuda_bf16.h>
#include <math.h>
#include <mma.h>

using namespace nvcuda;

// ---------------------------------------------------------------------------
// Problem constants
// ---------------------------------------------------------------------------
#define NN     50000
#define DD     200
#define KK     3
#define R2D    474
#define EE     250000
#define BB     2048
#define HH     100
#define KD     (KK*DD)          // 600
#define NPAIR  3

// ---------------------------------------------------------------------------
// Scratch (static device globals)
// ---------------------------------------------------------------------------
__device__ float g_x[(size_t)NN * KD];        // x after PCA+tanh   (120 MB)
__device__ float g_agg[(size_t)NN * KD];      // normalized attention aggregate
__device__ float g_xi[(size_t)NPAIR * BB * DD];
__device__ float g_hmu[(size_t)NPAIR * BB * HH];
__device__ float g_hlv[(size_t)NPAIR * BB * HH];
__device__ float g_mu[(size_t)NPAIR * BB * DD];
__device__ float g_lv[(size_t)NPAIR * BB * DD];
// CSR scratch
__device__ int g_deg[NN];
__device__ int g_off[NN + 1];
__device__ int g_cur[NN];
__device__ int g_eord[EE];

// ---------------------------------------------------------------------------
// Zero small scratch (deg + loss)
// ---------------------------------------------------------------------------
__global__ void zero_small_kernel(float* __restrict__ loss_slot)
{
    int i = blockIdx.x * blockDim.x + threadIdx.x;
    if (i < NN) g_deg[i] = 0;
    if (i == 0) *loss_slot = 0.f;
}

// ---------------------------------------------------------------------------
// CSR build: histogram -> scan -> scatter
// ---------------------------------------------------------------------------
__global__ void hist_kernel(const int* __restrict__ ei)
{
    int e = blockIdx.x * blockDim.x + threadIdx.x;
    if (e < EE) atomicAdd(&g_deg[ei[e]], 1);   // ei[0..EE) = dst
}

__global__ __launch_bounds__(1024)
void scan_kernel()
{
    __shared__ int part[1024];
    const int t = threadIdx.x;
    const int CH = (NN + 1023) / 1024;         // 49
    int s = 0;
#pragma unroll 4
    for (int i = 0; i < CH; i++) {
        int idx = t * CH + i;
        if (idx < NN) s += g_deg[idx];
    }
    part[t] = s;
    __syncthreads();
    int own = s;
    for (int o = 1; o < 1024; o <<= 1) {
        int v = part[t];
        if (t >= o) v += part[t - o];
        __syncthreads();
        part[t] = v;
        __syncthreads();
    }
    int base = part[t] - own;                  // exclusive prefix
    int run = base;
    for (int i = 0; i < CH; i++) {
        int idx = t * CH + i;
        if (idx < NN) {
            g_off[idx] = run;
            g_cur[idx] = run;
            run += g_deg[idx];
        }
    }
    if (t == 0) g_off[NN] = EE;
}

__global__ void scatter_kernel(const int* __restrict__ ei)
{
    int e = blockIdx.x * blockDim.x + threadIdx.x;
    if (e < EE) {
        int d = ei[e];
        int p = atomicAdd(&g_cur[d], 1);
        g_eord[p] = e;
    }
}

// ---------------------------------------------------------------------------
// Fused attention pass. One warp per destination node.
//   For each incoming edge e: msg = x[src]*r[et];  dot_k = <x[dst,k], msg_k>
//   a = exp(leaky(dot_k * relw[et,k]));  S_k += a*msg_k;  D_k += a
//   agg[dst,k,:] = S_k / (D_k + 1e-10)
// (segment-max cancels exactly in alpha up to the 1e-10 eps; |logit|<=~1.)
// ---------------------------------------------------------------------------
__global__ __launch_bounds__(256)
void node_attn_kernel(const int* __restrict__ ei, const int* __restrict__ etype,
                      const float* __restrict__ r, const float* __restrict__ relw)
{
    int w    = (blockIdx.x * blockDim.x + threadIdx.x) >> 5;
    int lane = threadIdx.x & 31;
    if (w >= NN) return;
    const int node = w;

    const float* xd = g_x + (size_t)node * KD;
    float xdv[KK][7];
#pragma unroll
    for (int k = 0; k < KK; k++)
#pragma unroll
        for (int i = 0; i < 7; i++) {
            int d = lane + 32 * i;
            xdv[k][i] = (d < DD) ? xd[k * DD + d] : 0.f;
        }

    float acc[KK][7];
    float den[KK];
#pragma unroll
    for (int k = 0; k < KK; k++) {
        den[k] = 0.f;
#pragma unroll
        for (int i = 0; i < 7; i++) acc[k][i] = 0.f;
    }

    const int beg = g_off[node];
    const int end = g_off[node + 1];
    for (int p = beg; p < end; p++) {
        int e   = g_eord[p];
        int src = ei[EE + e];
        int t   = etype[e];
        const float* xs = g_x + (size_t)src * KD;
        const float* rr = r   + (size_t)t * DD;

        float rv[7];
#pragma unroll
        for (int i = 0; i < 7; i++) {
            int d = lane + 32 * i;
            rv[i] = (d < DD) ? rr[d] : 0.f;
        }

        float msg[KK][7];
        float dot[KK];
#pragma unroll
        for (int k = 0; k < KK; k++) {
            dot[k] = 0.f;
#pragma unroll
            for (int i = 0; i < 7; i++) {
                int d = lane + 32 * i;
                float m = (d < DD) ? xs[k * DD + d] * rv[i] : 0.f;
                msg[k][i] = m;
                dot[k] += xdv[k][i] * m;
            }
        }
#pragma unroll
        for (int k = 0; k < KK; k++)
#pragma unroll
            for (int o = 16; o > 0; o >>= 1)
                dot[k] += __shfl_xor_sync(0xffffffffu, dot[k], o);

#pragma unroll
        for (int k = 0; k < KK; k++) {
            float l = dot[k] * relw[t * KK + k];
            l = (l > 0.f) ? l : 0.2f * l;
            float a = expf(l);
            den[k] += a;
#pragma unroll
            for (int i = 0; i < 7; i++) acc[k][i] += a * msg[k][i];
        }
    }

    float* ag = g_agg + (size_t)node * KD;
#pragma unroll
    for (int k = 0; k < KK; k++) {
        float inv = 1.f / (den[k] + 1e-10f);
#pragma unroll
        for (int i = 0; i < 7; i++) {
            int d = lane + 32 * i;
            if (d < DD) ag[k * DD + d] = acc[k][i] * inv;
        }
    }
}

// ---------------------------------------------------------------------------
// tf32 tensor-core GEMM with bias + activation (unchanged from R3).
// ---------------------------------------------------------------------------
#define TM 128
#define TN 64
#define TKC 16

template<int ACT, bool BIAS>
__global__ __launch_bounds__(256)
void gemm_tf32_kernel(const float* __restrict__ A, const float* __restrict__ B,
                      const float* __restrict__ bias, float* __restrict__ C,
                      int M, int N, int Kd)
{
    __shared__ float As[TM][TKC + 4];
    __shared__ float Bs[TKC][TN + 4];
    __shared__ float Cs[TM][TN];

    const int tid  = threadIdx.x;
    const int warp = tid >> 5;
    const int wm   = warp >> 1;
    const int wn   = warp & 1;
    const int row0 = blockIdx.y * TM;
    const int col0 = blockIdx.x * TN;

    wmma::fragment<wmma::accumulator, 16, 16, 8, float> acc[2][2];
#pragma unroll
    for (int i = 0; i < 2; i++)
#pragma unroll
        for (int j = 0; j < 2; j++)
            wmma::fill_fragment(acc[i][j], 0.0f);

    for (int k0 = 0; k0 < Kd; k0 += TKC) {
#pragma unroll
        for (int l = 0; l < 8; l++) {
            int idx = tid + l * 256;
            int m  = idx >> 4;
            int kk = idx & 15;
            int gr = row0 + m, gk = k0 + kk;
            As[m][kk] = (gr < M && gk < Kd) ? A[(size_t)gr * Kd + gk] : 0.f;
        }
#pragma unroll
        for (int l = 0; l < 4; l++) {
            int idx = tid + l * 256;
            int n  = idx & 63;
            int kk = idx >> 6;
            int gk = k0 + kk, gc = col0 + n;
            Bs[kk][n] = (gk < Kd && gc < N) ? B[(size_t)gk * N + gc] : 0.f;
        }
        __syncthreads();

#pragma unroll
        for (int ks = 0; ks < TKC; ks += 8) {
            wmma::fragment<wmma::matrix_a, 16, 16, 8,
                           wmma::precision::tf32, wmma::row_major> fa[2];
            wmma::fragment<wmma::matrix_b, 16, 16, 8,
                           wmma::precision::tf32, wmma::row_major> fb[2];
#pragma unroll
            for (int i = 0; i < 2; i++) {
                wmma::load_matrix_sync(fa[i], &As[wm * 32 + i * 16][ks], TKC + 4);
#pragma unroll
                for (int t = 0; t < fa[i].num_elements; t++)
                    fa[i].x[t] = wmma::__float_to_tf32(fa[i].x[t]);
            }
#pragma unroll
            for (int j = 0; j < 2; j++) {
                wmma::load_matrix_sync(fb[j], &Bs[ks][wn * 32 + j * 16], TN + 4);
#pragma unroll
                for (int t = 0; t < fb[j].num_elements; t++)
                    fb[j].x[t] = wmma::__float_to_tf32(fb[j].x[t]);
            }
#pragma unroll
            for (int i = 0; i < 2; i++)
#pragma unroll
                for (int j = 0; j < 2; j++)
                    wmma::mma_sync(acc[i][j], fa[i], fb[j], acc[i][j]);
        }
        __syncthreads();
    }

#pragma unroll
    for (int i = 0; i < 2; i++)
#pragma unroll
        for (int j = 0; j < 2; j++)
            wmma::store_matrix_sync(&Cs[wm * 32 + i * 16][wn * 32 + j * 16],
                                    acc[i][j], TN, wmma::mem_row_major);
    __syncthreads();

#pragma unroll
    for (int l = 0; l < (TM * TN) / 256; l++) {
        int idx = tid + l * 256;
        int m = idx / TN;
        int n = idx % TN;
        int gr = row0 + m, gc = col0 + n;
        if (gr < M && gc < N) {
            float v = Cs[m][n];
            if (BIAS) v += bias[gc];
            if (ACT == 1) v = tanhf(v);
            else if (ACT == 2) v = fmaxf(v, 0.f);
            C[(size_t)gr * N + gc] = v;
        }
    }
}

// ---------------------------------------------------------------------------
// Gather outputs: sub_emb, rel_emb_single, xi
// ---------------------------------------------------------------------------
__global__ __launch_bounds__(256)
void gather_kernel(const float* __restrict__ xnew, const float* __restrict__ init_rel,
                   const int* __restrict__ sub, const int* __restrict__ rel,
                   float* __restrict__ sub_emb, float* __restrict__ rel_emb)
{
    int b = blockIdx.x;
    int t = threadIdx.x;
    int sb = sub[b];
    const float* srcx = xnew + (size_t)sb * KD;
    float* se = sub_emb + (size_t)b * KD;
    for (int j = t; j < KD; j += 256) se[j] = srcx[j];

    int rb = rel[b];
    const float* srcr = init_rel + (size_t)rb * DD;
    float* re = rel_emb + (size_t)b * DD;
    for (int j = t; j < DD; j += 256) re[j] = srcr[j];

    for (int j = t; j < DD; j += 256) {
        float v0 = srcx[j];           // k = 0
        float v1 = srcx[DD + j];      // k = 1
        g_xi[((size_t)0 * BB + b) * DD + j] = v0;
        g_xi[((size_t)1 * BB + b) * DD + j] = v0;
        g_xi[((size_t)2 * BB + b) * DD + j] = v1;
    }
}

// ---------------------------------------------------------------------------
// MI loss reduction. One warp per (pair, batch element).
// ---------------------------------------------------------------------------
__global__ __launch_bounds__(256)
void mi_loss_kernel(const float* __restrict__ xnew,
                    const int* __restrict__ sub, const int* __restrict__ perm,
                    float* __restrict__ loss_out)
{
    int w    = (blockIdx.x * blockDim.x + threadIdx.x) >> 5;
    int lane = threadIdx.x & 31;
    if (w >= NPAIR * BB) return;
    int p = w / BB;
    int b = w % BB;
    int pj = (p == 0) ? 1 : 2;

    const float* mup = g_mu + ((size_t)p * BB + b) * DD;
    const float* lvp = g_lv + ((size_t)p * BB + b) * DD;
    int sb  = sub[b];
    int sbn = sub[perm[b]];
    const float* yj  = xnew + (size_t)sb  * KD + pj * DD;
    const float* yjn = xnew + (size_t)sbn * KD + pj * DD;

    float s = 0.f;
    for (int d = lane; d < DD; d += 32) {
        float m  = mup[d];
        float iv = expf(-lvp[d]);
        float dp = m - yj[d];
        float dn = m - yjn[d];
        s += (dn * dn - dp * dp) * iv;
    }
#pragma unroll
    for (int o = 16; o > 0; o >>= 1)
        s += __shfl_xor_sync(0xffffffffu, s, o);
    if (lane == 0)
        atomicAdd(loss_out, s / (2.0f * BB));
}

// ---------------------------------------------------------------------------
// Launch
// ---------------------------------------------------------------------------
extern "C" void kernel_launch(void* const* d_in, const int* in_sizes, int n_in,
                              void* d_out, int out_size)
{
    const float *init_embed, *init_rel, *pca_W, *pca_b, *rel_weight, *W_ent;
    const float *mu_w1, *mu_b1, *mu_w2, *mu_b2, *lv_w1, *lv_b1, *lv_w2, *lv_b2;
    const int *edge_index, *edge_type, *sub, *rel, *perm;

    if (in_sizes[0] == 2 * EE) {
        // dict order
        edge_index = (const int*)d_in[0];
        edge_type  = (const int*)d_in[1];
        sub        = (const int*)d_in[2];
        rel        = (const int*)d_in[3];
        perm       = (const int*)d_in[4];
        init_embed = (const float*)d_in[5];
        init_rel   = (const float*)d_in[6];
        pca_W      = (const float*)d_in[7];
        pca_b      = (const float*)d_in[8];
        rel_weight = (const float*)d_in[9];
        W_ent      = (const float*)d_in[10];
        /* d_in[11] = W_rel (dead) */
        mu_w1 = (const float*)d_in[12];
        mu_b1 = (const float*)d_in[13];
        mu_w2 = (const float*)d_in[14];
        mu_b2 = (const float*)d_in[15];
        lv_w1 = (const float*)d_in[16];
        lv_b1 = (const float*)d_in[17];
        lv_w2 = (const float*)d_in[18];
        lv_b2 = (const float*)d_in[19];
    } else {
        // signature order
        init_embed = (const float*)d_in[0];
        init_rel   = (const float*)d_in[1];
        pca_W      = (const float*)d_in[2];
        pca_b      = (const float*)d_in[3];
        rel_weight = (const float*)d_in[4];
        W_ent      = (const float*)d_in[5];
        mu_w1 = (const float*)d_in[7];
        mu_b1 = (const float*)d_in[8];
        mu_w2 = (const float*)d_in[9];
        mu_b2 = (const float*)d_in[10];
        lv_w1 = (const float*)d_in[11];
        lv_b1 = (const float*)d_in[12];
        lv_w2 = (const float*)d_in[13];
        lv_b2 = (const float*)d_in[14];
        edge_index = (const int*)d_in[15];
        edge_type  = (const int*)d_in[16];
        sub        = (const int*)d_in[17];
        rel        = (const int*)d_in[18];
        perm       = (const int*)d_in[19];
    }

    float* out = (float*)d_out;
    const size_t SUB_OFF  = 0;
    const size_t REL_OFF  = (size_t)BB * KD;
    const size_t X_OFF    = REL_OFF + (size_t)BB * DD;
    const size_t LOSS_OFF = X_OFF + (size_t)NN * KD;

    float* sub_emb = out + SUB_OFF;
    float* rel_emb = out + REL_OFF;
    float* xnew    = out + X_OFF;
    float* loss    = out + LOSS_OFF;

    float *p_x, *p_agg, *p_xi, *p_hmu, *p_hlv, *p_mu, *p_lv;
    cudaGetSymbolAddress((void**)&p_x,   g_x);
    cudaGetSymbolAddress((void**)&p_agg, g_agg);
    cudaGetSymbolAddress((void**)&p_xi,  g_xi);
    cudaGetSymbolAddress((void**)&p_hmu, g_hmu);
    cudaGetSymbolAddress((void**)&p_hlv, g_hlv);
    cudaGetSymbolAddress((void**)&p_mu,  g_mu);
    cudaGetSymbolAddress((void**)&p_lv,  g_lv);

    // 1. zero deg + loss; build CSR (overlappable with GEMM below in-stream)
    zero_small_kernel<<<(NN + 255) / 256, 256>>>(loss);
    hist_kernel<<<(EE + 255) / 256, 256>>>(edge_index);
    scan_kernel<<<1, 1024>>>();
    scatter_kernel<<<(EE + 255) / 256, 256>>>(edge_index);

    // 2. x = tanh(init_embed @ pca_W + pca_b)   (50000 x 600)
    {
        dim3 g((KD + TN - 1) / TN, (NN + TM - 1) / TM);
        gemm_tf32_kernel<1, true><<<g, 256>>>(init_embed, pca_W, pca_b, p_x,
                                              NN, KD, DD);
    }

    // 3. fused attention pass (logits + softmax + aggregate), warp per node
    {
        int blocks = (NN * 32 + 255) / 256;
        node_attn_kernel<<<blocks, 256>>>(edge_index, edge_type,
                                          init_rel, rel_weight);
    }

    // 4. x_new = tanh(agg @ W_ent)  ((N*K) x 200)
    {
        dim3 g((DD + TN - 1) / TN, (NN * KK + TM - 1) / TM);
        gemm_tf32_kernel<1, false><<<g, 256>>>(p_agg, W_ent, nullptr, xnew,
                                               NN * KK, DD, DD);
    }

    // 5. gathers: sub_emb, rel_emb, xi
    gather_kernel<<<BB, 256>>>(xnew, init_rel, sub, rel, sub_emb, rel_emb);

    // 6. MI head per pair: two 2-layer MLPs
    for (int p = 0; p < NPAIR; p++) {
        const float* xi_p = p_xi + (size_t)p * BB * DD;
        {
            dim3 g((HH + TN - 1) / TN, (BB + TM - 1) / TM);
            gemm_tf32_kernel<2, true><<<g, 256>>>(xi_p,
                mu_w1 + (size_t)p * DD * HH, mu_b1 + (size_t)p * HH,
                p_hmu + (size_t)p * BB * HH, BB, HH, DD);
        }
        {
            dim3 g((DD + TN - 1) / TN, (BB + TM - 1) / TM);
            gemm_tf32_kernel<0, true><<<g, 256>>>(p_hmu + (size_t)p * BB * HH,
                mu_w2 + (size_t)p * HH * DD, mu_b2 + (size_t)p * DD,
                p_mu + (size_t)p * BB * DD, BB, DD, HH);
        }
        {
            dim3 g((HH + TN - 1) / TN, (BB + TM - 1) / TM);
            gemm_tf32_kernel<2, true><<<g, 256>>>(xi_p,
                lv_w1 + (size_t)p * DD * HH, lv_b1 + (size_t)p * HH,
                p_hlv + (size_t)p * BB * HH, BB, HH, DD);
        }
        {
            dim3 g((DD + TN - 1) / TN, (BB + TM - 1) / TM);
            gemm_tf32_kernel<1, true><<<g, 256>>>(p_hlv + (size_t)p * BB * HH,
                lv_w2 + (size_t)p * HH * DD, lv_b2 + (size_t)p * DD,
                p_lv + (size_t)p * BB * DD, BB, DD, HH);
        }
    }

    // 7. MI loss reduction
    {
        int blocks = (NPAIR * BB * 32 + 255) / 256;
        mi_loss_kernel<<<blocks, 256>>>(xnew, sub, perm, loss);
    }

    (void)n_in; (void)out_size;
}

// round 6
// speedup vs baseline: 2.1248x; 1.3020x over previous
#include <cuda_runtime.h>
#include <cuda_bf16.h>
#include <math.h>
#include <mma.h>
#include <stdint.h>

using namespace nvcuda;

// ---------------------------------------------------------------------------
// Problem constants
// ---------------------------------------------------------------------------
#define NN     50000
#define DD     200
#define KK     3
#define R2D    474
#define EE     250000
#define BB     2048
#define HH     100
#define KD     (KK*DD)          // 600
#define NPAIR  3

// ---------------------------------------------------------------------------
// Scratch (static device globals). 16B alignment for float4 / cp.async paths.
// ---------------------------------------------------------------------------
__device__ __align__(16) float g_x[(size_t)NN * KD];
__device__ __align__(16) float g_agg[(size_t)NN * KD];
__device__ __align__(16) float g_xi[(size_t)NPAIR * BB * DD];
__device__ __align__(16) float g_hmu[(size_t)NPAIR * BB * HH];
__device__ __align__(16) float g_hlv[(size_t)NPAIR * BB * HH];
__device__ __align__(16) float g_mu[(size_t)NPAIR * BB * DD];
__device__ __align__(16) float g_lv[(size_t)NPAIR * BB * DD];
// CSR scratch
__device__ int g_deg[NN];
__device__ int g_off[NN + 1];
__device__ int g_cur[NN];
__device__ int g_eord[EE];

// ---------------------------------------------------------------------------
// cp.async helpers
// ---------------------------------------------------------------------------
__device__ __forceinline__ void cp_async16(void* sdst, const void* gsrc, bool pred)
{
    uint32_t s = (uint32_t)__cvta_generic_to_shared(sdst);
    int sz = pred ? 16 : 0;
    asm volatile("cp.async.cg.shared.global [%0], [%1], 16, %2;\n"
                 :: "r"(s), "l"(gsrc), "r"(sz));
}
__device__ __forceinline__ void cp_commit()
{
    asm volatile("cp.async.commit_group;\n");
}
template<int N> __device__ __forceinline__ void cp_wait()
{
    asm volatile("cp.async.wait_group %0;\n" :: "n"(N));
}

// ---------------------------------------------------------------------------
// Zero small scratch (deg + loss)
// ---------------------------------------------------------------------------
__global__ void zero_small_kernel(float* __restrict__ loss_slot)
{
    int i = blockIdx.x * blockDim.x + threadIdx.x;
    if (i < NN) g_deg[i] = 0;
    if (i == 0) *loss_slot = 0.f;
}

// ---------------------------------------------------------------------------
// CSR build: histogram -> scan -> scatter
// ---------------------------------------------------------------------------
__global__ void hist_kernel(const int* __restrict__ ei)
{
    int e = blockIdx.x * blockDim.x + threadIdx.x;
    if (e < EE) atomicAdd(&g_deg[ei[e]], 1);
}

__global__ __launch_bounds__(1024)
void scan_kernel()
{
    __shared__ int part[1024];
    const int t = threadIdx.x;
    const int CH = (NN + 1023) / 1024;
    int s = 0;
#pragma unroll 4
    for (int i = 0; i < CH; i++) {
        int idx = t * CH + i;
        if (idx < NN) s += g_deg[idx];
    }
    part[t] = s;
    __syncthreads();
    int own = s;
    for (int o = 1; o < 1024; o <<= 1) {
        int v = part[t];
        if (t >= o) v += part[t - o];
        __syncthreads();
        part[t] = v;
        __syncthreads();
    }
    int run = part[t] - own;
    for (int i = 0; i < CH; i++) {
        int idx = t * CH + i;
        if (idx < NN) {
            g_off[idx] = run;
            g_cur[idx] = run;
            run += g_deg[idx];
        }
    }
    if (t == 0) g_off[NN] = EE;
}

__global__ void scatter_kernel(const int* __restrict__ ei)
{
    int e = blockIdx.x * blockDim.x + threadIdx.x;
    if (e < EE) {
        int d = ei[e];
        int p = atomicAdd(&g_cur[d], 1);
        g_eord[p] = e;
    }
}

// ---------------------------------------------------------------------------
// Fused attention pass. One warp per (node, k). float4 loads.
//   agg[dst,k,:] = (sum_e a_e * msg_e) / (sum_e a_e + 1e-10)
//   a_e = exp(leaky(<x[dst,k],msg_k> * relw[et,k])), msg = x[src,k]*r[et]
// ---------------------------------------------------------------------------
__global__ __launch_bounds__(256)
void node_attn_kernel(const int* __restrict__ ei, const int* __restrict__ etype,
                      const float* __restrict__ r, const float* __restrict__ relw)
{
    int w    = (blockIdx.x * blockDim.x + threadIdx.x) >> 5;
    int lane = threadIdx.x & 31;
    if (w >= NN * KK) return;
    const int node = w / KK;
    const int k    = w - node * KK;

    const float4* xd4 = reinterpret_cast<const float4*>(g_x + (size_t)node * KD + k * DD);
    float4 xd0 = xd4[lane];
    float4 xd1 = (lane < 18) ? xd4[lane + 32] : make_float4(0.f, 0.f, 0.f, 0.f);

    float4 acc0 = make_float4(0.f, 0.f, 0.f, 0.f);
    float4 acc1 = make_float4(0.f, 0.f, 0.f, 0.f);
    float  den  = 0.f;

    const int beg = g_off[node];
    const int end = g_off[node + 1];
    for (int p = beg; p < end; p++) {
        int e   = g_eord[p];
        int src = ei[EE + e];
        int t   = etype[e];
        const float4* xs4 = reinterpret_cast<const float4*>(g_x + (size_t)src * KD + k * DD);
        const float4* rr4 = reinterpret_cast<const float4*>(r + (size_t)t * DD);

        float4 a0 = xs4[lane];
        float4 r0 = rr4[lane];
        float4 m0 = make_float4(a0.x * r0.x, a0.y * r0.y, a0.z * r0.z, a0.w * r0.w);
        float4 m1 = make_float4(0.f, 0.f, 0.f, 0.f);
        if (lane < 18) {
            float4 a1 = xs4[lane + 32];
            float4 r1 = rr4[lane + 32];
            m1 = make_float4(a1.x * r1.x, a1.y * r1.y, a1.z * r1.z, a1.w * r1.w);
        }
        float dot = xd0.x * m0.x + xd0.y * m0.y + xd0.z * m0.z + xd0.w * m0.w
                  + xd1.x * m1.x + xd1.y * m1.y + xd1.z * m1.z + xd1.w * m1.w;
#pragma unroll
        for (int o = 16; o > 0; o >>= 1)
            dot += __shfl_xor_sync(0xffffffffu, dot, o);

        float l = dot * relw[t * KK + k];
        l = (l > 0.f) ? l : 0.2f * l;
        float a = expf(l);
        den += a;
        acc0.x += a * m0.x; acc0.y += a * m0.y; acc0.z += a * m0.z; acc0.w += a * m0.w;
        acc1.x += a * m1.x; acc1.y += a * m1.y; acc1.z += a * m1.z; acc1.w += a * m1.w;
    }

    float inv = 1.f / (den + 1e-10f);
    float4* ag4 = reinterpret_cast<float4*>(g_agg + (size_t)node * KD + k * DD);
    ag4[lane] = make_float4(acc0.x * inv, acc0.y * inv, acc0.z * inv, acc0.w * inv);
    if (lane < 18)
        ag4[lane + 32] = make_float4(acc1.x * inv, acc1.y * inv, acc1.z * inv, acc1.w * inv);
}

// ---------------------------------------------------------------------------
// tf32 GEMM core: 128x64 block tile, cp.async double-buffered, SMEM reuse
// for the C epilogue tile. act: 0=none 1=tanh 2=relu. bias may be null.
// ---------------------------------------------------------------------------
#define TM 128
#define TN 64
#define TKC 16
#define AS_STRIDE (TKC + 4)              // 20
#define BS_STRIDE (TN + 4)               // 68
#define AS_SIZE   (TM * AS_STRIDE)       // 2560 floats
#define BS_SIZE   (TKC * BS_STRIDE)      // 1088 floats
#define SM_FLOATS (TM * TN)              // 8192 floats = 32KB (>= 2*(AS+BS)=7296)

__device__ __forceinline__ void stage_load(
    const float* __restrict__ A, const float* __restrict__ B,
    int M, int N, int Kd, int row0, int col0, int k0,
    float* Asb, float* Bsb)
{
    const int tid = threadIdx.x;
    // A tile: 128 rows x 4 chunks(16B) = 512 chunks, 2 per thread
#pragma unroll
    for (int l = 0; l < 2; l++) {
        int c = tid + l * 256;
        int m = c >> 2, q = (c & 3) * 4;
        int gr = row0 + m, gk = k0 + q;
        bool pr = (gr < M) && (gk < Kd);          // Kd % 4 == 0 always
        const float* gp = pr ? (A + (size_t)gr * Kd + gk) : A;
        cp_async16(&Asb[m * AS_STRIDE + q], gp, pr);
    }
    // B tile: 16 rows x 16 chunks = 256 chunks, 1 per thread
    {
        int kk = tid >> 4, q = (tid & 15) * 4;
        int gk = k0 + kk, gc = col0 + q;
        bool pr = (gk < Kd) && (gc < N);          // N % 4 == 0 always
        const float* gp = pr ? (B + (size_t)gk * N + gc) : B;
        cp_async16(&Bsb[kk * BS_STRIDE + q], gp, pr);
    }
    cp_commit();
}

__device__ __forceinline__ void gemm_core(
    const float* __restrict__ A, const float* __restrict__ B,
    const float* __restrict__ bias, float* __restrict__ C,
    int M, int N, int Kd, int act, float* sm)
{
    float* As0 = sm;
    float* As1 = sm + AS_SIZE;
    float* Bs0 = sm + 2 * AS_SIZE;
    float* Bs1 = sm + 2 * AS_SIZE + BS_SIZE;

    const int tid  = threadIdx.x;
    const int warp = tid >> 5;
    const int wm   = warp >> 1;
    const int wn   = warp & 1;
    const int row0 = blockIdx.y * TM;
    const int col0 = blockIdx.x * TN;

    wmma::fragment<wmma::accumulator, 16, 16, 8, float> acc[2][2];
#pragma unroll
    for (int i = 0; i < 2; i++)
#pragma unroll
        for (int j = 0; j < 2; j++)
            wmma::fill_fragment(acc[i][j], 0.0f);

    const int NK = (Kd + TKC - 1) / TKC;
    stage_load(A, B, M, N, Kd, row0, col0, 0, As0, Bs0);

    for (int kt = 0; kt < NK; kt++) {
        float* Asb = (kt & 1) ? As1 : As0;
        float* Bsb = (kt & 1) ? Bs1 : Bs0;
        if (kt + 1 < NK) {
            float* An = ((kt + 1) & 1) ? As1 : As0;
            float* Bn = ((kt + 1) & 1) ? Bs1 : Bs0;
            stage_load(A, B, M, N, Kd, row0, col0, (kt + 1) * TKC, An, Bn);
            cp_wait<1>();
        } else {
            cp_wait<0>();
        }
        __syncthreads();

#pragma unroll
        for (int ks = 0; ks < TKC; ks += 8) {
            wmma::fragment<wmma::matrix_a, 16, 16, 8,
                           wmma::precision::tf32, wmma::row_major> fa[2];
            wmma::fragment<wmma::matrix_b, 16, 16, 8,
                           wmma::precision::tf32, wmma::row_major> fb[2];
#pragma unroll
            for (int i = 0; i < 2; i++) {
                wmma::load_matrix_sync(fa[i], &Asb[(wm * 32 + i * 16) * AS_STRIDE + ks],
                                       AS_STRIDE);
#pragma unroll
                for (int t = 0; t < fa[i].num_elements; t++)
                    fa[i].x[t] = wmma::__float_to_tf32(fa[i].x[t]);
            }
#pragma unroll
            for (int j = 0; j < 2; j++) {
                wmma::load_matrix_sync(fb[j], &Bsb[ks * BS_STRIDE + wn * 32 + j * 16],
                                       BS_STRIDE);
#pragma unroll
                for (int t = 0; t < fb[j].num_elements; t++)
                    fb[j].x[t] = wmma::__float_to_tf32(fb[j].x[t]);
            }
#pragma unroll
            for (int i = 0; i < 2; i++)
#pragma unroll
                for (int j = 0; j < 2; j++)
                    wmma::mma_sync(acc[i][j], fa[i], fb[j], acc[i][j]);
        }
        __syncthreads();
    }

    // epilogue: reuse smem as C tile
    float* Cs = sm;
#pragma unroll
    for (int i = 0; i < 2; i++)
#pragma unroll
        for (int j = 0; j < 2; j++)
            wmma::store_matrix_sync(&Cs[(wm * 32 + i * 16) * TN + wn * 32 + j * 16],
                                    acc[i][j], TN, wmma::mem_row_major);
    __syncthreads();

#pragma unroll
    for (int l = 0; l < (TM * TN) / 256; l++) {
        int idx = tid + l * 256;
        int m = idx / TN;
        int n = idx % TN;
        int gr = row0 + m, gc = col0 + n;
        if (gr < M && gc < N) {
            float v = Cs[m * TN + n];
            if (bias) v += bias[gc];
            if (act == 1) v = tanhf(v);
            else if (act == 2) v = fmaxf(v, 0.f);
            C[(size_t)gr * N + gc] = v;
        }
    }
}

__global__ __launch_bounds__(256)
void gemm_tf32_kernel(const float* __restrict__ A, const float* __restrict__ B,
                      const float* __restrict__ bias, float* __restrict__ C,
                      int M, int N, int Kd, int act)
{
    __shared__ float sm[SM_FLOATS];
    gemm_core(A, B, bias, C, M, N, Kd, act, sm);
}

// Batched MI layer-1: z in [0,6): p = z>>1, lv = z&1. relu activation.
__global__ __launch_bounds__(256)
void mi_l1_kernel(const float* __restrict__ mu_w1, const float* __restrict__ mu_b1,
                  const float* __restrict__ lv_w1, const float* __restrict__ lv_b1)
{
    __shared__ float sm[SM_FLOATS];
    int z = blockIdx.z, p = z >> 1, lv = z & 1;
    const float* A    = g_xi + (size_t)p * BB * DD;
    const float* B    = (lv ? lv_w1 : mu_w1) + (size_t)p * DD * HH;
    const float* bias = (lv ? lv_b1 : mu_b1) + (size_t)p * HH;
    float*       C    = (lv ? g_hlv : g_hmu) + (size_t)p * BB * HH;
    gemm_core(A, B, bias, C, BB, HH, DD, 2, sm);
}

// Batched MI layer-2: mu -> no act, lv -> tanh.
__global__ __launch_bounds__(256)
void mi_l2_kernel(const float* __restrict__ mu_w2, const float* __restrict__ mu_b2,
                  const float* __restrict__ lv_w2, const float* __restrict__ lv_b2)
{
    __shared__ float sm[SM_FLOATS];
    int z = blockIdx.z, p = z >> 1, lv = z & 1;
    const float* A    = (lv ? g_hlv : g_hmu) + (size_t)p * BB * HH;
    const float* B    = (lv ? lv_w2 : mu_w2) + (size_t)p * HH * DD;
    const float* bias = (lv ? lv_b2 : mu_b2) + (size_t)p * DD;
    float*       C    = (lv ? g_lv : g_mu) + (size_t)p * BB * DD;
    gemm_core(A, B, bias, C, BB, DD, HH, lv ? 1 : 0, sm);
}

// ---------------------------------------------------------------------------
// Gather outputs: sub_emb, rel_emb_single, xi
// ---------------------------------------------------------------------------
__global__ __launch_bounds__(256)
void gather_kernel(const float* __restrict__ xnew, const float* __restrict__ init_rel,
                   const int* __restrict__ sub, const int* __restrict__ rel,
                   float* __restrict__ sub_emb, float* __restrict__ rel_emb)
{
    int b = blockIdx.x;
    int t = threadIdx.x;
    int sb = sub[b];
    const float* srcx = xnew + (size_t)sb * KD;
    float* se = sub_emb + (size_t)b * KD;
    for (int j = t; j < KD; j += 256) se[j] = srcx[j];

    int rb = rel[b];
    const float* srcr = init_rel + (size_t)rb * DD;
    float* re = rel_emb + (size_t)b * DD;
    for (int j = t; j < DD; j += 256) re[j] = srcr[j];

    for (int j = t; j < DD; j += 256) {
        float v0 = srcx[j];           // k = 0
        float v1 = srcx[DD + j];      // k = 1
        g_xi[((size_t)0 * BB + b) * DD + j] = v0;
        g_xi[((size_t)1 * BB + b) * DD + j] = v0;
        g_xi[((size_t)2 * BB + b) * DD + j] = v1;
    }
}

// ---------------------------------------------------------------------------
// MI loss reduction. One warp per (pair, batch element).
// ---------------------------------------------------------------------------
__global__ __launch_bounds__(256)
void mi_loss_kernel(const float* __restrict__ xnew,
                    const int* __restrict__ sub, const int* __restrict__ perm,
                    float* __restrict__ loss_out)
{
    int w    = (blockIdx.x * blockDim.x + threadIdx.x) >> 5;
    int lane = threadIdx.x & 31;
    if (w >= NPAIR * BB) return;
    int p = w / BB;
    int b = w % BB;
    int pj = (p == 0) ? 1 : 2;

    const float* mup = g_mu + ((size_t)p * BB + b) * DD;
    const float* lvp = g_lv + ((size_t)p * BB + b) * DD;
    int sb  = sub[b];
    int sbn = sub[perm[b]];
    const float* yj  = xnew + (size_t)sb  * KD + pj * DD;
    const float* yjn = xnew + (size_t)sbn * KD + pj * DD;

    float s = 0.f;
    for (int d = lane; d < DD; d += 32) {
        float m  = mup[d];
        float iv = expf(-lvp[d]);
        float dp = m - yj[d];
        float dn = m - yjn[d];
        s += (dn * dn - dp * dp) * iv;
    }
#pragma unroll
    for (int o = 16; o > 0; o >>= 1)
        s += __shfl_xor_sync(0xffffffffu, s, o);
    if (lane == 0)
        atomicAdd(loss_out, s / (2.0f * BB));
}

// ---------------------------------------------------------------------------
// Launch
// ---------------------------------------------------------------------------
extern "C" void kernel_launch(void* const* d_in, const int* in_sizes, int n_in,
                              void* d_out, int out_size)
{
    const float *init_embed, *init_rel, *pca_W, *pca_b, *rel_weight, *W_ent;
    const float *mu_w1, *mu_b1, *mu_w2, *mu_b2, *lv_w1, *lv_b1, *lv_w2, *lv_b2;
    const int *edge_index, *edge_type, *sub, *rel, *perm;

    if (in_sizes[0] == 2 * EE) {
        // dict order
        edge_index = (const int*)d_in[0];
        edge_type  = (const int*)d_in[1];
        sub        = (const int*)d_in[2];
        rel        = (const int*)d_in[3];
        perm       = (const int*)d_in[4];
        init_embed = (const float*)d_in[5];
        init_rel   = (const float*)d_in[6];
        pca_W      = (const float*)d_in[7];
        pca_b      = (const float*)d_in[8];
        rel_weight = (const float*)d_in[9];
        W_ent      = (const float*)d_in[10];
        /* d_in[11] = W_rel (dead) */
        mu_w1 = (const float*)d_in[12];
        mu_b1 = (const float*)d_in[13];
        mu_w2 = (const float*)d_in[14];
        mu_b2 = (const float*)d_in[15];
        lv_w1 = (const float*)d_in[16];
        lv_b1 = (const float*)d_in[17];
        lv_w2 = (const float*)d_in[18];
        lv_b2 = (const float*)d_in[19];
    } else {
        // signature order
        init_embed = (const float*)d_in[0];
        init_rel   = (const float*)d_in[1];
        pca_W      = (const float*)d_in[2];
        pca_b      = (const float*)d_in[3];
        rel_weight = (const float*)d_in[4];
        W_ent      = (const float*)d_in[5];
        mu_w1 = (const float*)d_in[7];
        mu_b1 = (const float*)d_in[8];
        mu_w2 = (const float*)d_in[9];
        mu_b2 = (const float*)d_in[10];
        lv_w1 = (const float*)d_in[11];
        lv_b1 = (const float*)d_in[12];
        lv_w2 = (const float*)d_in[13];
        lv_b2 = (const float*)d_in[14];
        edge_index = (const int*)d_in[15];
        edge_type  = (const int*)d_in[16];
        sub        = (const int*)d_in[17];
        rel        = (const int*)d_in[18];
        perm       = (const int*)d_in[19];
    }

    float* out = (float*)d_out;
    const size_t SUB_OFF  = 0;
    const size_t REL_OFF  = (size_t)BB * KD;
    const size_t X_OFF    = REL_OFF + (size_t)BB * DD;
    const size_t LOSS_OFF = X_OFF + (size_t)NN * KD;

    float* sub_emb = out + SUB_OFF;
    float* rel_emb = out + REL_OFF;
    float* xnew    = out + X_OFF;
    float* loss    = out + LOSS_OFF;

    float *p_x, *p_agg;
    cudaGetSymbolAddress((void**)&p_x,   g_x);
    cudaGetSymbolAddress((void**)&p_agg, g_agg);

    // 1. zero deg + loss; build CSR
    zero_small_kernel<<<(NN + 255) / 256, 256>>>(loss);
    hist_kernel<<<(EE + 255) / 256, 256>>>(edge_index);
    scan_kernel<<<1, 1024>>>();
    scatter_kernel<<<(EE + 255) / 256, 256>>>(edge_index);

    // 2. x = tanh(init_embed @ pca_W + pca_b)   (50000 x 600)
    {
        dim3 g((KD + TN - 1) / TN, (NN + TM - 1) / TM);
        gemm_tf32_kernel<<<g, 256>>>(init_embed, pca_W, pca_b, p_x,
                                     NN, KD, DD, 1);
    }

    // 3. fused attention pass, warp per (node,k)
    {
        int blocks = (NN * KK * 32 + 255) / 256;
        node_attn_kernel<<<blocks, 256>>>(edge_index, edge_type,
                                          init_rel, rel_weight);
    }

    // 4. x_new = tanh(agg @ W_ent)  ((N*K) x 200)
    {
        dim3 g((DD + TN - 1) / TN, (NN * KK + TM - 1) / TM);
        gemm_tf32_kernel<<<g, 256>>>(p_agg, W_ent, nullptr, xnew,
                                     NN * KK, DD, DD, 1);
    }

    // 5. gathers: sub_emb, rel_emb, xi
    gather_kernel<<<BB, 256>>>(xnew, init_rel, sub, rel, sub_emb, rel_emb);

    // 6. MI head: two batched launches (6 GEMMs each)
    {
        dim3 g1((HH + TN - 1) / TN, (BB + TM - 1) / TM, 6);
        mi_l1_kernel<<<g1, 256>>>(mu_w1, mu_b1, lv_w1, lv_b1);
        dim3 g2((DD + TN - 1) / TN, (BB + TM - 1) / TM, 6);
        mi_l2_kernel<<<g2, 256>>>(mu_w2, mu_b2, lv_w2, lv_b2);
    }

    // 7. MI loss reduction
    {
        int blocks = (NPAIR * BB * 32 + 255) / 256;
        mi_loss_kernel<<<blocks, 256>>>(xnew, sub, perm, loss);
    }

    (void)n_in; (void)out_size;
}

// round 8
// speedup vs baseline: 2.1356x; 1.0051x over previous
#include <cuda_runtime.h>
#include <cuda_bf16.h>
#include <math.h>
#include <mma.h>
#include <stdint.h>

using namespace nvcuda;

// ---------------------------------------------------------------------------
// Problem constants
// ---------------------------------------------------------------------------
#define NN     50000
#define DD     200
#define KK     3
#define R2D    474
#define EE     250000
#define BB     2048
#define HH     100
#define KD     (KK*DD)          // 600
#define NPAIR  3

// ---------------------------------------------------------------------------
// Scratch (static device globals). 16B alignment for float4 / cp.async paths.
// ---------------------------------------------------------------------------
__device__ __align__(16) float g_x[(size_t)NN * KD];
__device__ __align__(16) float g_agg[(size_t)NN * KD];
__device__ __align__(16) float g_xi[(size_t)NPAIR * BB * DD];
__device__ __align__(16) float g_hmu[(size_t)NPAIR * BB * HH];
__device__ __align__(16) float g_hlv[(size_t)NPAIR * BB * HH];
__device__ __align__(16) float g_mu[(size_t)NPAIR * BB * DD];
__device__ __align__(16) float g_lv[(size_t)NPAIR * BB * DD];
// CSR scratch
__device__ int g_deg[NN];
__device__ int g_off[NN + 1];
__device__ int g_cur[NN];
__device__ int g_eord[EE];

// ---------------------------------------------------------------------------
// cp.async helpers
// ---------------------------------------------------------------------------
__device__ __forceinline__ void cp_async16(void* sdst, const void* gsrc, bool pred)
{
    uint32_t s = (uint32_t)__cvta_generic_to_shared(sdst);
    int sz = pred ? 16 : 0;
    asm volatile("cp.async.cg.shared.global [%0], [%1], 16, %2;\n"
                 :: "r"(s), "l"(gsrc), "r"(sz));
}
__device__ __forceinline__ void cp_commit()
{
    asm volatile("cp.async.commit_group;\n");
}
template<int N> __device__ __forceinline__ void cp_wait()
{
    asm volatile("cp.async.wait_group %0;\n" :: "n"(N));
}

// ---------------------------------------------------------------------------
// Zero small scratch (deg + loss)
// ---------------------------------------------------------------------------
__global__ void zero_small_kernel(float* __restrict__ loss_slot)
{
    int i = blockIdx.x * blockDim.x + threadIdx.x;
    if (i < NN) g_deg[i] = 0;
    if (i == 0) *loss_slot = 0.f;
}

// ---------------------------------------------------------------------------
// CSR build: histogram -> scan -> scatter
// ---------------------------------------------------------------------------
__global__ void hist_kernel(const int* __restrict__ ei)
{
    int e = blockIdx.x * blockDim.x + threadIdx.x;
    if (e < EE) atomicAdd(&g_deg[ei[e]], 1);
}

__global__ __launch_bounds__(1024)
void scan_kernel()
{
    __shared__ int part[1024];
    const int t = threadIdx.x;
    const int CH = (NN + 1023) / 1024;
    int s = 0;
#pragma unroll 4
    for (int i = 0; i < CH; i++) {
        int idx = t * CH + i;
        if (idx < NN) s += g_deg[idx];
    }
    part[t] = s;
    __syncthreads();
    int own = s;
    for (int o = 1; o < 1024; o <<= 1) {
        int v = part[t];
        if (t >= o) v += part[t - o];
        __syncthreads();
        part[t] = v;
        __syncthreads();
    }
    int run = part[t] - own;
    for (int i = 0; i < CH; i++) {
        int idx = t * CH + i;
        if (idx < NN) {
            g_off[idx] = run;
            g_cur[idx] = run;
            run += g_deg[idx];
        }
    }
    if (t == 0) g_off[NN] = EE;
}

__global__ void scatter_kernel(const int* __restrict__ ei)
{
    int e = blockIdx.x * blockDim.x + threadIdx.x;
    if (e < EE) {
        int d = ei[e];
        int p = atomicAdd(&g_cur[d], 1);
        g_eord[p] = e;
    }
}

// ---------------------------------------------------------------------------
// Fused attention pass. One warp per (node, k). float4 loads.
// Two edges in flight per loop iteration for MLP (latency-bound loop).
//   agg[dst,k,:] = (sum_e a_e * msg_e) / (sum_e a_e + 1e-10)
//   a_e = exp(leaky(<x[dst,k],msg_k> * relw[et,k])), msg = x[src,k]*r[et]
// ---------------------------------------------------------------------------
__global__ __launch_bounds__(256)
void node_attn_kernel(const int* __restrict__ ei, const int* __restrict__ etype,
                      const float* __restrict__ r, const float* __restrict__ relw)
{
    int w    = (blockIdx.x * blockDim.x + threadIdx.x) >> 5;
    int lane = threadIdx.x & 31;
    if (w >= NN * KK) return;
    const int node = w / KK;
    const int k    = w - node * KK;

    const float4* xd4 = reinterpret_cast<const float4*>(g_x + (size_t)node * KD + k * DD);
    float4 xd0 = xd4[lane];
    float4 xd1 = (lane < 18) ? xd4[lane + 32] : make_float4(0.f, 0.f, 0.f, 0.f);

    float4 acc0 = make_float4(0.f, 0.f, 0.f, 0.f);
    float4 acc1 = make_float4(0.f, 0.f, 0.f, 0.f);
    float  den  = 0.f;

    const int beg = g_off[node];
    const int end = g_off[node + 1];
    int p = beg;

    // two edges per iteration
    for (; p + 1 < end; p += 2) {
        int e0 = g_eord[p];
        int e1 = g_eord[p + 1];
        int src0 = ei[EE + e0], t0 = etype[e0];
        int src1 = ei[EE + e1], t1 = etype[e1];
        float rw0 = relw[t0 * KK + k];
        float rw1 = relw[t1 * KK + k];

        const float4* xsA = reinterpret_cast<const float4*>(g_x + (size_t)src0 * KD + k * DD);
        const float4* rrA = reinterpret_cast<const float4*>(r + (size_t)t0 * DD);
        const float4* xsB = reinterpret_cast<const float4*>(g_x + (size_t)src1 * KD + k * DD);
        const float4* rrB = reinterpret_cast<const float4*>(r + (size_t)t1 * DD);

        // issue all 8 loads up front (independent)
        float4 aA0 = xsA[lane];
        float4 aB0 = xsB[lane];
        float4 rA0 = rrA[lane];
        float4 rB0 = rrB[lane];
        float4 aA1 = make_float4(0.f,0.f,0.f,0.f), rA1 = aA1;
        float4 aB1 = aA1, rB1 = aA1;
        if (lane < 18) {
            aA1 = xsA[lane + 32];
            aB1 = xsB[lane + 32];
            rA1 = rrA[lane + 32];
            rB1 = rrB[lane + 32];
        }

        float4 mA0 = make_float4(aA0.x*rA0.x, aA0.y*rA0.y, aA0.z*rA0.z, aA0.w*rA0.w);
        float4 mA1 = make_float4(aA1.x*rA1.x, aA1.y*rA1.y, aA1.z*rA1.z, aA1.w*rA1.w);
        float4 mB0 = make_float4(aB0.x*rB0.x, aB0.y*rB0.y, aB0.z*rB0.z, aB0.w*rB0.w);
        float4 mB1 = make_float4(aB1.x*rB1.x, aB1.y*rB1.y, aB1.z*rB1.z, aB1.w*rB1.w);

        float dotA = xd0.x*mA0.x + xd0.y*mA0.y + xd0.z*mA0.z + xd0.w*mA0.w
                   + xd1.x*mA1.x + xd1.y*mA1.y + xd1.z*mA1.z + xd1.w*mA1.w;
        float dotB = xd0.x*mB0.x + xd0.y*mB0.y + xd0.z*mB0.z + xd0.w*mB0.w
                   + xd1.x*mB1.x + xd1.y*mB1.y + xd1.z*mB1.z + xd1.w*mB1.w;
#pragma unroll
        for (int o = 16; o > 0; o >>= 1) {
            dotA += __shfl_xor_sync(0xffffffffu, dotA, o);
            dotB += __shfl_xor_sync(0xffffffffu, dotB, o);
        }

        float lA = dotA * rw0;  lA = (lA > 0.f) ? lA : 0.2f * lA;
        float lB = dotB * rw1;  lB = (lB > 0.f) ? lB : 0.2f * lB;
        float aE0 = __expf(lA);
        float aE1 = __expf(lB);
        den += aE0 + aE1;
        acc0.x += aE0*mA0.x + aE1*mB0.x;  acc0.y += aE0*mA0.y + aE1*mB0.y;
        acc0.z += aE0*mA0.z + aE1*mB0.z;  acc0.w += aE0*mA0.w + aE1*mB0.w;
        acc1.x += aE0*mA1.x + aE1*mB1.x;  acc1.y += aE0*mA1.y + aE1*mB1.y;
        acc1.z += aE0*mA1.z + aE1*mB1.z;  acc1.w += aE0*mA1.w + aE1*mB1.w;
    }

    // tail edge
    if (p < end) {
        int e   = g_eord[p];
        int src = ei[EE + e];
        int t   = etype[e];
        float rw = relw[t * KK + k];
        const float4* xs4 = reinterpret_cast<const float4*>(g_x + (size_t)src * KD + k * DD);
        const float4* rr4 = reinterpret_cast<const float4*>(r + (size_t)t * DD);

        float4 a0 = xs4[lane];
        float4 r0 = rr4[lane];
        float4 m0 = make_float4(a0.x*r0.x, a0.y*r0.y, a0.z*r0.z, a0.w*r0.w);
        float4 m1 = make_float4(0.f, 0.f, 0.f, 0.f);
        if (lane < 18) {
            float4 a1 = xs4[lane + 32];
            float4 r1 = rr4[lane + 32];
            m1 = make_float4(a1.x*r1.x, a1.y*r1.y, a1.z*r1.z, a1.w*r1.w);
        }
        float dot = xd0.x*m0.x + xd0.y*m0.y + xd0.z*m0.z + xd0.w*m0.w
                  + xd1.x*m1.x + xd1.y*m1.y + xd1.z*m1.z + xd1.w*m1.w;
#pragma unroll
        for (int o = 16; o > 0; o >>= 1)
            dot += __shfl_xor_sync(0xffffffffu, dot, o);

        float l = dot * rw;
        l = (l > 0.f) ? l : 0.2f * l;
        float a = __expf(l);
        den += a;
        acc0.x += a*m0.x; acc0.y += a*m0.y; acc0.z += a*m0.z; acc0.w += a*m0.w;
        acc1.x += a*m1.x; acc1.y += a*m1.y; acc1.z += a*m1.z; acc1.w += a*m1.w;
    }

    float inv = 1.f / (den + 1e-10f);
    float4* ag4 = reinterpret_cast<float4*>(g_agg + (size_t)node * KD + k * DD);
    ag4[lane] = make_float4(acc0.x * inv, acc0.y * inv, acc0.z * inv, acc0.w * inv);
    if (lane < 18)
        ag4[lane + 32] = make_float4(acc1.x * inv, acc1.y * inv, acc1.z * inv, acc1.w * inv);
}

// ---------------------------------------------------------------------------
// tf32 GEMM core: 128x64 block tile, cp.async double-buffered, SMEM reuse
// for the C epilogue tile. act: 0=none 1=tanh 2=relu. bias may be null.
// ---------------------------------------------------------------------------
#define TM 128
#define TN 64
#define TKC 16
#define AS_STRIDE (TKC + 4)              // 20
#define BS_STRIDE (TN + 4)               // 68
#define AS_SIZE   (TM * AS_STRIDE)       // 2560 floats
#define BS_SIZE   (TKC * BS_STRIDE)      // 1088 floats
#define SM_FLOATS (TM * TN)              // 8192 floats = 32KB (>= 2*(AS+BS)=7296)

__device__ __forceinline__ void stage_load(
    const float* __restrict__ A, const float* __restrict__ B,
    int M, int N, int Kd, int row0, int col0, int k0,
    float* Asb, float* Bsb)
{
    const int tid = threadIdx.x;
#pragma unroll
    for (int l = 0; l < 2; l++) {
        int c = tid + l * 256;
        int m = c >> 2, q = (c & 3) * 4;
        int gr = row0 + m, gk = k0 + q;
        bool pr = (gr < M) && (gk < Kd);
        const float* gp = pr ? (A + (size_t)gr * Kd + gk) : A;
        cp_async16(&Asb[m * AS_STRIDE + q], gp, pr);
    }
    {
        int kk = tid >> 4, q = (tid & 15) * 4;
        int gk = k0 + kk, gc = col0 + q;
        bool pr = (gk < Kd) && (gc < N);
        const float* gp = pr ? (B + (size_t)gk * N + gc) : B;
        cp_async16(&Bsb[kk * BS_STRIDE + q], gp, pr);
    }
    cp_commit();
}

__device__ __forceinline__ void gemm_core(
    const float* __restrict__ A, const float* __restrict__ B,
    const float* __restrict__ bias, float* __restrict__ C,
    int M, int N, int Kd, int act, float* sm)
{
    float* As0 = sm;
    float* As1 = sm + AS_SIZE;
    float* Bs0 = sm + 2 * AS_SIZE;
    float* Bs1 = sm + 2 * AS_SIZE + BS_SIZE;

    const int tid  = threadIdx.x;
    const int warp = tid >> 5;
    const int wm   = warp >> 1;
    const int wn   = warp & 1;
    const int row0 = blockIdx.y * TM;
    const int col0 = blockIdx.x * TN;

    wmma::fragment<wmma::accumulator, 16, 16, 8, float> acc[2][2];
#pragma unroll
    for (int i = 0; i < 2; i++)
#pragma unroll
        for (int j = 0; j < 2; j++)
            wmma::fill_fragment(acc[i][j], 0.0f);

    const int NK = (Kd + TKC - 1) / TKC;
    stage_load(A, B, M, N, Kd, row0, col0, 0, As0, Bs0);

    for (int kt = 0; kt < NK; kt++) {
        float* Asb = (kt & 1) ? As1 : As0;
        float* Bsb = (kt & 1) ? Bs1 : Bs0;
        if (kt + 1 < NK) {
            float* An = ((kt + 1) & 1) ? As1 : As0;
            float* Bn = ((kt + 1) & 1) ? Bs1 : Bs0;
            stage_load(A, B, M, N, Kd, row0, col0, (kt + 1) * TKC, An, Bn);
            cp_wait<1>();
        } else {
            cp_wait<0>();
        }
        __syncthreads();

#pragma unroll
        for (int ks = 0; ks < TKC; ks += 8) {
            wmma::fragment<wmma::matrix_a, 16, 16, 8,
                           wmma::precision::tf32, wmma::row_major> fa[2];
            wmma::fragment<wmma::matrix_b, 16, 16, 8,
                           wmma::precision::tf32, wmma::row_major> fb[2];
#pragma unroll
            for (int i = 0; i < 2; i++) {
                wmma::load_matrix_sync(fa[i], &Asb[(wm * 32 + i * 16) * AS_STRIDE + ks],
                                       AS_STRIDE);
#pragma unroll
                for (int t = 0; t < fa[i].num_elements; t++)
                    fa[i].x[t] = wmma::__float_to_tf32(fa[i].x[t]);
            }
#pragma unroll
            for (int j = 0; j < 2; j++) {
                wmma::load_matrix_sync(fb[j], &Bsb[ks * BS_STRIDE + wn * 32 + j * 16],
                                       BS_STRIDE);
#pragma unroll
                for (int t = 0; t < fb[j].num_elements; t++)
                    fb[j].x[t] = wmma::__float_to_tf32(fb[j].x[t]);
            }
#pragma unroll
            for (int i = 0; i < 2; i++)
#pragma unroll
                for (int j = 0; j < 2; j++)
                    wmma::mma_sync(acc[i][j], fa[i], fb[j], acc[i][j]);
        }
        __syncthreads();
    }

    float* Cs = sm;
#pragma unroll
    for (int i = 0; i < 2; i++)
#pragma unroll
        for (int j = 0; j < 2; j++)
            wmma::store_matrix_sync(&Cs[(wm * 32 + i * 16) * TN + wn * 32 + j * 16],
                                    acc[i][j], TN, wmma::mem_row_major);
    __syncthreads();

#pragma unroll
    for (int l = 0; l < (TM * TN) / 256; l++) {
        int idx = tid + l * 256;
        int m = idx / TN;
        int n = idx % TN;
        int gr = row0 + m, gc = col0 + n;
        if (gr < M && gc < N) {
            float v = Cs[m * TN + n];
            if (bias) v += bias[gc];
            if (act == 1) v = tanhf(v);
            else if (act == 2) v = fmaxf(v, 0.f);
            C[(size_t)gr * N + gc] = v;
        }
    }
}

__global__ __launch_bounds__(256)
void gemm_tf32_kernel(const float* __restrict__ A, const float* __restrict__ B,
                      const float* __restrict__ bias, float* __restrict__ C,
                      int M, int N, int Kd, int act)
{
    __shared__ float sm[SM_FLOATS];
    gemm_core(A, B, bias, C, M, N, Kd, act, sm);
}

// Batched MI layer-1: z in [0,6): p = z>>1, lv = z&1. relu activation.
__global__ __launch_bounds__(256)
void mi_l1_kernel(const float* __restrict__ mu_w1, const float* __restrict__ mu_b1,
                  const float* __restrict__ lv_w1, const float* __restrict__ lv_b1)
{
    __shared__ float sm[SM_FLOATS];
    int z = blockIdx.z, p = z >> 1, lv = z & 1;
    const float* A    = g_xi + (size_t)p * BB * DD;
    const float* B    = (lv ? lv_w1 : mu_w1) + (size_t)p * DD * HH;
    const float* bias = (lv ? lv_b1 : mu_b1) + (size_t)p * HH;
    float*       C    = (lv ? g_hlv : g_hmu) + (size_t)p * BB * HH;
    gemm_core(A, B, bias, C, BB, HH, DD, 2, sm);
}

// Batched MI layer-2: mu -> no act, lv -> tanh.
__global__ __launch_bounds__(256)
void mi_l2_kernel(const float* __restrict__ mu_w2, const float* __restrict__ mu_b2,
                  const float* __restrict__ lv_w2, const float* __restrict__ lv_b2)
{
    __shared__ float sm[SM_FLOATS];
    int z = blockIdx.z, p = z >> 1, lv = z & 1;
    const float* A    = (lv ? g_hlv : g_hmu) + (size_t)p * BB * HH;
    const float* B    = (lv ? lv_w2 : mu_w2) + (size_t)p * HH * DD;
    const float* bias = (lv ? lv_b2 : mu_b2) + (size_t)p * DD;
    float*       C    = (lv ? g_lv : g_mu) + (size_t)p * BB * DD;
    gemm_core(A, B, bias, C, BB, DD, HH, lv ? 1 : 0, sm);
}

// ---------------------------------------------------------------------------
// Gather outputs: sub_emb, rel_emb_single, xi
// ---------------------------------------------------------------------------
__global__ __launch_bounds__(256)
void gather_kernel(const float* __restrict__ xnew, const float* __restrict__ init_rel,
                   const int* __restrict__ sub, const int* __restrict__ rel,
                   float* __restrict__ sub_emb, float* __restrict__ rel_emb)
{
    int b = blockIdx.x;
    int t = threadIdx.x;
    int sb = sub[b];
    const float* srcx = xnew + (size_t)sb * KD;
    float* se = sub_emb + (size_t)b * KD;
    for (int j = t; j < KD; j += 256) se[j] = srcx[j];

    int rb = rel[b];
    const float* srcr = init_rel + (size_t)rb * DD;
    float* re = rel_emb + (size_t)b * DD;
    for (int j = t; j < DD; j += 256) re[j] = srcr[j];

    for (int j = t; j < DD; j += 256) {
        float v0 = srcx[j];           // k = 0
        float v1 = srcx[DD + j];      // k = 1
        g_xi[((size_t)0 * BB + b) * DD + j] = v0;
        g_xi[((size_t)1 * BB + b) * DD + j] = v0;
        g_xi[((size_t)2 * BB + b) * DD + j] = v1;
    }
}

// ---------------------------------------------------------------------------
// MI loss reduction. One warp per (pair, batch element).
// ---------------------------------------------------------------------------
__global__ __launch_bounds__(256)
void mi_loss_kernel(const float* __restrict__ xnew,
                    const int* __restrict__ sub, const int* __restrict__ perm,
                    float* __restrict__ loss_out)
{
    int w    = (blockIdx.x * blockDim.x + threadIdx.x) >> 5;
    int lane = threadIdx.x & 31;
    if (w >= NPAIR * BB) return;
    int p = w / BB;
    int b = w % BB;
    int pj = (p == 0) ? 1 : 2;

    const float* mup = g_mu + ((size_t)p * BB + b) * DD;
    const float* lvp = g_lv + ((size_t)p * BB + b) * DD;
    int sb  = sub[b];
    int sbn = sub[perm[b]];
    const float* yj  = xnew + (size_t)sb  * KD + pj * DD;
    const float* yjn = xnew + (size_t)sbn * KD + pj * DD;

    float s = 0.f;
    for (int d = lane; d < DD; d += 32) {
        float m  = mup[d];
        float iv = expf(-lvp[d]);
        float dp = m - yj[d];
        float dn = m - yjn[d];
        s += (dn * dn - dp * dp) * iv;
    }
#pragma unroll
    for (int o = 16; o > 0; o >>= 1)
        s += __shfl_xor_sync(0xffffffffu, s, o);
    if (lane == 0)
        atomicAdd(loss_out, s / (2.0f * BB));
}

// ---------------------------------------------------------------------------
// Launch
// ---------------------------------------------------------------------------
extern "C" void kernel_launch(void* const* d_in, const int* in_sizes, int n_in,
                              void* d_out, int out_size)
{
    const float *init_embed, *init_rel, *pca_W, *pca_b, *rel_weight, *W_ent;
    const float *mu_w1, *mu_b1, *mu_w2, *mu_b2, *lv_w1, *lv_b1, *lv_w2, *lv_b2;
    const int *edge_index, *edge_type, *sub, *rel, *perm;

    if (in_sizes[0] == 2 * EE) {
        // dict order
        edge_index = (const int*)d_in[0];
        edge_type  = (const int*)d_in[1];
        sub        = (const int*)d_in[2];
        rel        = (const int*)d_in[3];
        perm       = (const int*)d_in[4];
        init_embed = (const float*)d_in[5];
        init_rel   = (const float*)d_in[6];
        pca_W      = (const float*)d_in[7];
        pca_b      = (const float*)d_in[8];
        rel_weight = (const float*)d_in[9];
        W_ent      = (const float*)d_in[10];
        /* d_in[11] = W_rel (dead) */
        mu_w1 = (const float*)d_in[12];
        mu_b1 = (const float*)d_in[13];
        mu_w2 = (const float*)d_in[14];
        mu_b2 = (const float*)d_in[15];
        lv_w1 = (const float*)d_in[16];
        lv_b1 = (const float*)d_in[17];
        lv_w2 = (const float*)d_in[18];
        lv_b2 = (const float*)d_in[19];
    } else {
        // signature order
        init_embed = (const float*)d_in[0];
        init_rel   = (const float*)d_in[1];
        pca_W      = (const float*)d_in[2];
        pca_b      = (const float*)d_in[3];
        rel_weight = (const float*)d_in[4];
        W_ent      = (const float*)d_in[5];
        mu_w1 = (const float*)d_in[7];
        mu_b1 = (const float*)d_in[8];
        mu_w2 = (const float*)d_in[9];
        mu_b2 = (const float*)d_in[10];
        lv_w1 = (const float*)d_in[11];
        lv_b1 = (const float*)d_in[12];
        lv_w2 = (const float*)d_in[13];
        lv_b2 = (const float*)d_in[14];
        edge_index = (const int*)d_in[15];
        edge_type  = (const int*)d_in[16];
        sub        = (const int*)d_in[17];
        rel        = (const int*)d_in[18];
        perm       = (const int*)d_in[19];
    }

    float* out = (float*)d_out;
    const size_t SUB_OFF  = 0;
    const size_t REL_OFF  = (size_t)BB * KD;
    const size_t X_OFF    = REL_OFF + (size_t)BB * DD;
    const size_t LOSS_OFF = X_OFF + (size_t)NN * KD;

    float* sub_emb = out + SUB_OFF;
    float* rel_emb = out + REL_OFF;
    float* xnew    = out + X_OFF;
    float* loss    = out + LOSS_OFF;

    float *p_x, *p_agg;
    cudaGetSymbolAddress((void**)&p_x,   g_x);
    cudaGetSymbolAddress((void**)&p_agg, g_agg);

    // 1. zero deg + loss; build CSR
    zero_small_kernel<<<(NN + 255) / 256, 256>>>(loss);
    hist_kernel<<<(EE + 255) / 256, 256>>>(edge_index);
    scan_kernel<<<1, 1024>>>();
    scatter_kernel<<<(EE + 255) / 256, 256>>>(edge_index);

    // 2. x = tanh(init_embed @ pca_W + pca_b)   (50000 x 600)
    {
        dim3 g((KD + TN - 1) / TN, (NN + TM - 1) / TM);
        gemm_tf32_kernel<<<g, 256>>>(init_embed, pca_W, pca_b, p_x,
                                     NN, KD, DD, 1);
    }

    // 3. fused attention pass, warp per (node,k), 2 edges in flight
    {
        int blocks = (NN * KK * 32 + 255) / 256;
        node_attn_kernel<<<blocks, 256>>>(edge_index, edge_type,
                                          init_rel, rel_weight);
    }

    // 4. x_new = tanh(agg @ W_ent)  ((N*K) x 200)
    {
        dim3 g((DD + TN - 1) / TN, (NN * KK + TM - 1) / TM);
        gemm_tf32_kernel<<<g, 256>>>(p_agg, W_ent, nullptr, xnew,
                                     NN * KK, DD, DD, 1);
    }

    // 5. gathers: sub_emb, rel_emb, xi
    gather_kernel<<<BB, 256>>>(xnew, init_rel, sub, rel, sub_emb, rel_emb);

    // 6. MI head: two batched launches (6 GEMMs each)
    {
        dim3 g1((HH + TN - 1) / TN, (BB + TM - 1) / TM, 6);
        mi_l1_kernel<<<g1, 256>>>(mu_w1, mu_b1, lv_w1, lv_b1);
        dim3 g2((DD + TN - 1) / TN, (BB + TM - 1) / TM, 6);
        mi_l2_kernel<<<g2, 256>>>(mu_w2, mu_b2, lv_w2, lv_b2);
    }

    // 7. MI loss reduction
    {
        int blocks = (NPAIR * BB * 32 + 255) / 256;
        mi_loss_kernel<<<blocks, 256>>>(xnew, sub, perm, loss);
    }

    (void)n_in; (void)out_size;
}